// round 12
// baseline (speedup 1.0000x reference)
#include <cuda_runtime.h>
#include <cuda_bf16.h>
#include <cstdint>

#define B_  4
#define S_  2048
#define C_  1024
#define H_  16
#define D_  64
#define M_  (B_*S_)     // 8192
#define N3_ (3*C_)      // 3072

// Scratch (no allocations allowed)
__device__ __align__(16) __nv_bfloat16 g_qh[B_*H_*S_*D_];
__device__ __align__(16) __nv_bfloat16 g_ql[B_*H_*S_*D_];
__device__ __align__(16) __nv_bfloat16 g_kh[B_*H_*S_*D_];
__device__ __align__(16) __nv_bfloat16 g_kl[B_*H_*S_*D_];
__device__ __align__(16) __nv_bfloat16 g_vh[B_*H_*S_*D_];
__device__ __align__(16) __nv_bfloat16 g_vl[B_*H_*S_*D_];
// A operands, segmented: per row, per 16-k group: [16 hi | 16 lo] bf16
__device__ __align__(16) __nv_bfloat16 g_xa [M_*C_*2];
__device__ __align__(16) __nv_bfloat16 g_aoa[M_*C_*2];
// Weight planes (row-major [K][N]) bf16 hi/lo
__device__ __align__(16) __nv_bfloat16 g_wah[C_*N3_], g_wal[C_*N3_];
__device__ __align__(16) __nv_bfloat16 g_wph[C_*C_],  g_wpl[C_*C_];

// ---------------------------------------------------------------------------
// helpers
// ---------------------------------------------------------------------------
__device__ __forceinline__ unsigned pk2(float a, float b) {
    __nv_bfloat162 t = __floats2bfloat162_rn(a, b);
    return *reinterpret_cast<const unsigned*>(&t);
}
__device__ __forceinline__ float bfhi(float x) {
    return __bfloat162float(__float2bfloat16_rn(x));
}
__device__ __forceinline__ void ldsm4(unsigned r[4], unsigned addr) {
    asm volatile("ldmatrix.sync.aligned.m8n8.x4.shared.b16 {%0,%1,%2,%3}, [%4];\n"
        : "=r"(r[0]), "=r"(r[1]), "=r"(r[2]), "=r"(r[3]) : "r"(addr));
}
__device__ __forceinline__ void ldsm4t(unsigned r[4], unsigned addr) {
    asm volatile("ldmatrix.sync.aligned.m8n8.x4.trans.shared.b16 {%0,%1,%2,%3}, [%4];\n"
        : "=r"(r[0]), "=r"(r[1]), "=r"(r[2]), "=r"(r[3]) : "r"(addr));
}
__device__ __forceinline__ void mma16816(float c[4], const unsigned a[4],
                                         const unsigned b[2]) {
    asm volatile(
        "mma.sync.aligned.m16n8k16.row.col.f32.bf16.bf16.f32 "
        "{%0,%1,%2,%3}, {%4,%5,%6,%7}, {%8,%9}, {%0,%1,%2,%3};\n"
        : "+f"(c[0]), "+f"(c[1]), "+f"(c[2]), "+f"(c[3])
        : "r"(a[0]), "r"(a[1]), "r"(a[2]), "r"(a[3]), "r"(b[0]), "r"(b[1]));
}
__device__ __forceinline__ void cpa16(unsigned dst, const void* src) {
    asm volatile("cp.async.cg.shared.global [%0], [%1], 16;\n"
        :: "r"(dst), "l"(__cvta_generic_to_global(src)));
}
#define CP_COMMIT() asm volatile("cp.async.commit_group;\n" ::: "memory")
#define CP_WAIT1()  asm volatile("cp.async.wait_group 1;\n" ::: "memory")
#define CP_WAIT0()  asm volatile("cp.async.wait_group 0;\n" ::: "memory")

// ---------------------------------------------------------------------------
// Conversion kernels (memory-bound, run once)
// ---------------------------------------------------------------------------
__global__ __launch_bounds__(256) void conv_seg_x(const float* __restrict__ src)
{
    size_t s = (size_t)blockIdx.x * 256 + threadIdx.x;   // 16-elem segment id
    const float4* p = (const float4*)(src + s * 16);
    float4 a = p[0], b = p[1], c = p[2], d = p[3];
    __nv_bfloat16* dst = g_xa + s * 32;
    uint4 u;
    u.x = pk2(a.x, a.y); u.y = pk2(a.z, a.w);
    u.z = pk2(b.x, b.y); u.w = pk2(b.z, b.w);
    *(uint4*)dst = u;
    u.x = pk2(a.x - bfhi(a.x), a.y - bfhi(a.y));
    u.y = pk2(a.z - bfhi(a.z), a.w - bfhi(a.w));
    u.z = pk2(b.x - bfhi(b.x), b.y - bfhi(b.y));
    u.w = pk2(b.z - bfhi(b.z), b.w - bfhi(b.w));
    *(uint4*)(dst + 16) = u;
    u.x = pk2(c.x, c.y); u.y = pk2(c.z, c.w);
    u.z = pk2(d.x, d.y); u.w = pk2(d.z, d.w);
    *(uint4*)(dst + 8) = u;
    u.x = pk2(c.x - bfhi(c.x), c.y - bfhi(c.y));
    u.y = pk2(c.z - bfhi(c.z), c.w - bfhi(c.w));
    u.z = pk2(d.x - bfhi(d.x), d.y - bfhi(d.y));
    u.w = pk2(d.z - bfhi(d.z), d.w - bfhi(d.w));
    *(uint4*)(dst + 24) = u;
}

template<int P>   // 0 = W_attn, 1 = W_proj
__global__ __launch_bounds__(256) void conv_plane(const float* __restrict__ src)
{
    size_t i = ((size_t)blockIdx.x * 256 + threadIdx.x) * 8;
    const float4* p = (const float4*)(src + i);
    float4 a = p[0], b = p[1];
    __nv_bfloat16* dh = (P == 0) ? g_wah : g_wph;
    __nv_bfloat16* dl = (P == 0) ? g_wal : g_wpl;
    uint4 u;
    u.x = pk2(a.x, a.y); u.y = pk2(a.z, a.w);
    u.z = pk2(b.x, b.y); u.w = pk2(b.z, b.w);
    *(uint4*)(dh + i) = u;
    u.x = pk2(a.x - bfhi(a.x), a.y - bfhi(a.y));
    u.y = pk2(a.z - bfhi(a.z), a.w - bfhi(a.w));
    u.z = pk2(b.x - bfhi(b.x), b.y - bfhi(b.y));
    u.w = pk2(b.z - bfhi(b.z), b.w - bfhi(b.w));
    *(uint4*)(dl + i) = u;
}

// ---------------------------------------------------------------------------
// Tensor-core GEMM, bf16 hi/lo, BK=32 stages (32KB x 3 = 96KB dynamic smem),
// __launch_bounds__(256, 2): two CTAs per SM break barrier phase lock.
// UNCHANGED from R10 (proven 337us / tensor 75.7%).
// ---------------------------------------------------------------------------
template<int LDB, bool SCATTER>
__global__ __launch_bounds__(256, 2) void tc_gemm5(
    const float* __restrict__ bias, float* __restrict__ out)
{
    extern __shared__ __align__(16) unsigned char smem[];
    const unsigned sb = (unsigned)__cvta_generic_to_shared(smem);
    const __nv_bfloat16* Aseg = SCATTER ? g_xa  : g_aoa;
    const __nv_bfloat16* Whp  = SCATTER ? g_wah : g_wph;
    const __nv_bfloat16* Wlp  = SCATTER ? g_wal : g_wpl;

    const int tid = threadIdx.x, lane = tid & 31, warp = tid >> 5;
    const int mw = warp & 1, nw = warp >> 1;
    const int m0 = blockIdx.y << 7, n0 = blockIdx.x << 7;

    const int ar = tid >> 3, ac = tid & 7;
    const char* aSrc0 = (const char*)Aseg + (size_t)(m0 + ar) * 4096 + ac * 16;
    const unsigned aDst0 = ar * 128 + ((ac ^ (ar & 7)) << 4);
    const int bk = tid >> 4, bn = tid & 15;
    const char* bSrcH = (const char*)Whp + ((size_t)bk * LDB + n0 + bn * 8) * 2;
    const char* bSrcL = (const char*)Wlp + ((size_t)bk * LDB + n0 + bn * 8) * 2;
    const unsigned bDst0 = 16384 + bk * 256 + ((bn ^ (bk & 7)) << 4);
    const size_t bHalf = (size_t)16 * LDB * 2;
    const size_t bStep = (size_t)32 * LDB * 2;

    float acc[16][4];
#pragma unroll
    for (int i = 0; i < 16; i++)
#pragma unroll
        for (int j = 0; j < 4; j++) acc[i][j] = 0.f;

    auto issue = [&](int kt) {
        unsigned st = sb + (kt % 3) * 32768;
        const char* as = aSrc0 + (size_t)kt * 128;
#pragma unroll
        for (int i = 0; i < 4; i++)
            cpa16(st + aDst0 + i * 4096, as + (size_t)i * 131072);
        const char* bs = bSrcH + (size_t)kt * bStep;
        cpa16(st + bDst0,        bs);
        cpa16(st + bDst0 + 4096, bs + bHalf);
        const char* bl_ = bSrcL + (size_t)kt * bStep;
        cpa16(st + bDst0 + 8192,        bl_);
        cpa16(st + bDst0 + 8192 + 4096, bl_ + bHalf);
    };

    issue(0); CP_COMMIT();
    issue(1); CP_COMMIT();

    const int KT = C_ / 32;   // 32
    for (int kt = 0; kt < KT; kt++) {
        CP_WAIT1();
        __syncthreads();
        if (kt + 2 < KT) issue(kt + 2);
        CP_COMMIT();

        const unsigned sA  = sb + (kt % 3) * 32768;
        const unsigned sBh = sA + 16384, sBl = sA + 24576;

#pragma unroll
        for (int kc = 0; kc < 2; kc++) {
            unsigned ah[4][4], al[4][4], bh[2][4], bl[2][4];
#pragma unroll
            for (int mt = 0; mt < 4; mt++) {
                int row = mw * 64 + mt * 16 + (lane & 15);
                unsigned b128 = sA + row * 128;
                int chH = kc * 4 + (lane >> 4);
                int chL = kc * 4 + 2 + (lane >> 4);
                ldsm4(ah[mt], b128 + ((chH ^ (row & 7)) << 4));
                ldsm4(al[mt], b128 + ((chL ^ (row & 7)) << 4));
            }
#pragma unroll
            for (int tp = 0; tp < 2; tp++) {
                int k  = kc * 16 + (lane & 15);
                int nc = nw * 4 + tp * 2 + (lane >> 4);
                unsigned off = k * 256 + ((nc ^ (k & 7)) << 4);
                ldsm4t(bh[tp], sBh + off);
                ldsm4t(bl[tp], sBl + off);
            }
#pragma unroll
            for (int mt = 0; mt < 4; mt++)
#pragma unroll
                for (int tp = 0; tp < 2; tp++)
#pragma unroll
                    for (int hf = 0; hf < 2; hf++)
                        mma16816(acc[mt*4 + tp*2 + hf], ah[mt], bh[tp] + hf*2);
#pragma unroll
            for (int mt = 0; mt < 4; mt++)
#pragma unroll
                for (int tp = 0; tp < 2; tp++)
#pragma unroll
                    for (int hf = 0; hf < 2; hf++)
                        mma16816(acc[mt*4 + tp*2 + hf], ah[mt], bl[tp] + hf*2);
#pragma unroll
            for (int mt = 0; mt < 4; mt++)
#pragma unroll
                for (int tp = 0; tp < 2; tp++)
#pragma unroll
                    for (int hf = 0; hf < 2; hf++)
                        mma16816(acc[mt*4 + tp*2 + hf], al[mt], bh[tp] + hf*2);
        }
    }

    const int g  = lane >> 2;
    const int cp = (lane & 3) << 1;
    if (SCATTER) {
        const int part = n0 >> 10;
        __nv_bfloat16* dH = (part == 0) ? g_qh : (part == 1) ? g_kh : g_vh;
        __nv_bfloat16* dL = (part == 0) ? g_ql : (part == 1) ? g_kl : g_vl;
        const float fs = (part == 0) ? 0.125f : 1.0f;
#pragma unroll
        for (int mt = 0; mt < 4; mt++) {
#pragma unroll
            for (int nt = 0; nt < 4; nt++) {
                int n = n0 + nw * 32 + nt * 8 + cp;
                int c = n & (C_ - 1);
                int hh = c >> 6, d = c & 63;
                float b0 = bias[n], b1 = bias[n + 1];
                float* a4 = acc[mt * 4 + nt];
#pragma unroll
                for (int rr = 0; rr < 2; rr++) {
                    int m  = m0 + mw * 64 + mt * 16 + g + rr * 8;
                    int bb = m >> 11, ss = m & (S_ - 1);
                    float v0 = (a4[rr * 2] + b0) * fs;
                    float v1 = (a4[rr * 2 + 1] + b1) * fs;
                    float h0 = bfhi(v0), h1 = bfhi(v1);
                    size_t idx = (((size_t)(bb * H_ + hh)) * S_ + ss) * D_ + d;
                    *(unsigned*)&dH[idx] = pk2(v0, v1);
                    *(unsigned*)&dL[idx] = pk2(v0 - h0, v1 - h1);
                }
            }
        }
    } else {
#pragma unroll
        for (int mt = 0; mt < 4; mt++) {
#pragma unroll
            for (int nt = 0; nt < 4; nt++) {
                int n = n0 + nw * 32 + nt * 8 + cp;
                float b0 = bias[n], b1 = bias[n + 1];
                float* a4 = acc[mt * 4 + nt];
#pragma unroll
                for (int rr = 0; rr < 2; rr++) {
                    int m = m0 + mw * 64 + mt * 16 + g + rr * 8;
                    float2 o = make_float2(a4[rr * 2] + b0, a4[rr * 2 + 1] + b1);
                    *(float2*)&out[(size_t)m * C_ + n] = o;
                }
            }
        }
    }
}

// ---------------------------------------------------------------------------
// Flash attention fragment-load helpers (single-buffer)
// ---------------------------------------------------------------------------
__device__ __forceinline__ void load_kb(unsigned sKh, unsigned sKl, int kc, int lane,
                                        unsigned kbh[4][4], unsigned kbl[4][4]) {
#pragma unroll
    for (int ntp = 0; ntp < 4; ntp++) {
        int kr = ntp * 16 + ((lane >> 4) << 3) + (lane & 7);
        unsigned koff = kr * 128 +
            (((unsigned)((2 * kc + ((lane >> 3) & 1)) ^ (kr & 7))) << 4);
        ldsm4(kbh[ntp], sKh + koff);
        ldsm4(kbl[ntp], sKl + koff);
    }
}
__device__ __forceinline__ void load_vb(unsigned sVh, unsigned sVl, int kc, int lane,
                                        unsigned vbh[4][4], unsigned vbl[4][4]) {
#pragma unroll
    for (int dtp = 0; dtp < 4; dtp++) {
        int vr = kc * 16 + (lane & 15);
        unsigned voff = vr * 128 +
            (((unsigned)((2 * dtp + (lane >> 4)) ^ (vr & 7))) << 4);
        ldsm4t(vbh[dtp], sVh + voff);
        ldsm4t(vbl[dtp], sVl + voff);
    }
}

// ---------------------------------------------------------------------------
// Tensor-core flash attention: 256 threads (8 warps), 128 queries per CTA,
// 64-key tiles, D=64. K/V traffic per query HALVED vs 64q version.
// smem: Q 32KB + 2x32KB KV ring = 96KB. __launch_bounds__(256,2):
// 2 CTAs/SM -> 4 warps/SMSP hide softmax MUFU/shfl chains.
// Causal: ntiles = 2*qt+2; masking in last two key tiles (global compare).
// ---------------------------------------------------------------------------
__global__ __launch_bounds__(256, 2) void flash_attn_tc()
{
    extern __shared__ __align__(16) unsigned char fsm[];
    const unsigned sb = (unsigned)__cvta_generic_to_shared(fsm);
    const unsigned sQh = sb, sQl = sb + 16384;

    const int tid  = threadIdx.x;
    const int lane = tid & 31, warp = tid >> 5;
    const int bh = blockIdx.y;
    const int q0 = blockIdx.x << 7;
    const size_t base = (size_t)bh * (S_ * D_);
    const int g = lane >> 2, t4 = lane & 3;

    // Q tile: 128 rows hi/lo via plain loads (once)
#pragma unroll
    for (int i = 0; i < 4; i++) {
        int f = i * 256 + tid;
        int r = f >> 3, ch = f & 7;
        unsigned off = r * 128 + (((unsigned)(ch ^ (r & 7))) << 4);
        size_t src = base + (size_t)(q0 + r) * 64 + ch * 8;
        *(uint4*)(fsm + off)         = *(const uint4*)(g_qh + src);
        *(uint4*)(fsm + 16384 + off) = *(const uint4*)(g_ql + src);
    }

    auto issueKV = [&](int t) {
        unsigned stg = sb + 32768 + (t & 1) * 32768;
        size_t rowb = base + (size_t)(t << 6) * 64;
        const __nv_bfloat16* s0 = g_kh + rowb;
        const __nv_bfloat16* s1 = g_kl + rowb;
        const __nv_bfloat16* s2 = g_vh + rowb;
        const __nv_bfloat16* s3 = g_vl + rowb;
#pragma unroll
        for (int i = 0; i < 8; i++) {
            int idx = i * 256 + tid;        // 0..2047
            int arr = idx >> 9;
            int rem = idx & 511;
            int r = rem >> 3, ch = rem & 7;
            const __nv_bfloat16* sp = (arr == 0) ? s0 : (arr == 1) ? s1
                                     : (arr == 2) ? s2 : s3;
            cpa16(stg + arr * 8192 + r * 128 + ((ch ^ (r & 7)) << 4),
                  sp + (size_t)r * 64 + ch * 8);
        }
    };

    float o[8][4];
#pragma unroll
    for (int i = 0; i < 8; i++)
#pragma unroll
        for (int j = 0; j < 4; j++) o[i][j] = 0.f;
    float mr[2] = {-1e30f, -1e30f}, lr[2] = {0.f, 0.f};

    const int ntiles = 2 * blockIdx.x + 2;
    issueKV(0); CP_COMMIT();

    for (int t = 0; t < ntiles; t++) {
        if (t + 1 < ntiles) { issueKV(t + 1); CP_COMMIT(); CP_WAIT1(); }
        else                { CP_WAIT0(); }
        __syncthreads();   // stage t ready; also fences Q stores (t=0)

        const unsigned stg = sb + 32768 + (t & 1) * 32768;
        const unsigned sKh = stg, sKl = stg + 8192;
        const unsigned sVh = stg + 16384, sVl = stg + 24576;

        // ---- S = Q @ K^T, term-major ----
        float s[8][4];
#pragma unroll
        for (int i = 0; i < 8; i++)
#pragma unroll
            for (int j = 0; j < 4; j++) s[i][j] = 0.f;

#pragma unroll
        for (int kc = 0; kc < 4; kc++) {
            unsigned ah[4], al[4];
            int qr = warp * 16 + (lane & 15);
            unsigned qoff = qr * 128 +
                (((unsigned)((2 * kc + (lane >> 4)) ^ (qr & 7))) << 4);
            ldsm4(ah, sQh + qoff);
            ldsm4(al, sQl + qoff);
            unsigned kbh[4][4], kbl[4][4];
            load_kb(sKh, sKl, kc, lane, kbh, kbl);
#pragma unroll
            for (int ntp = 0; ntp < 4; ntp++) {
                mma16816(s[2*ntp],   ah, kbh[ntp]);
                mma16816(s[2*ntp+1], ah, kbh[ntp] + 2);
            }
#pragma unroll
            for (int ntp = 0; ntp < 4; ntp++) {
                mma16816(s[2*ntp],   ah, kbl[ntp]);
                mma16816(s[2*ntp+1], ah, kbl[ntp] + 2);
            }
#pragma unroll
            for (int ntp = 0; ntp < 4; ntp++) {
                mma16816(s[2*ntp],   al, kbh[ntp]);
                mma16816(s[2*ntp+1], al, kbh[ntp] + 2);
            }
        }

        // causal mask: only the last two key tiles can cross the diagonal
        if (t >= ntiles - 2) {
            const int k0 = t << 6;
            int row_lo = q0 + warp * 16 + g;
            int row_hi = row_lo + 8;
#pragma unroll
            for (int nt = 0; nt < 8; nt++) {
#pragma unroll
                for (int j = 0; j < 2; j++) {
                    int col = k0 + nt * 8 + 2 * t4 + j;
                    if (col > row_lo) s[nt][j]     = -1e30f;
                    if (col > row_hi) s[nt][2 + j] = -1e30f;
                }
            }
        }

        // ---- online softmax ----
#pragma unroll
        for (int hf = 0; hf < 2; hf++) {
            float mx = -1e30f;
#pragma unroll
            for (int nt = 0; nt < 8; nt++)
                mx = fmaxf(mx, fmaxf(s[nt][2*hf], s[nt][2*hf+1]));
            mx = fmaxf(mx, __shfl_xor_sync(0xffffffffu, mx, 1));
            mx = fmaxf(mx, __shfl_xor_sync(0xffffffffu, mx, 2));
            float mn   = fmaxf(mr[hf], mx);
            float corr = __expf(mr[hf] - mn);
            mr[hf] = mn;
            float rs = 0.f;
#pragma unroll
            for (int nt = 0; nt < 8; nt++) {
                float p0 = __expf(s[nt][2*hf]     - mn);
                float p1 = __expf(s[nt][2*hf + 1] - mn);
                s[nt][2*hf] = p0; s[nt][2*hf+1] = p1;
                rs += p0 + p1;
            }
            rs += __shfl_xor_sync(0xffffffffu, rs, 1);
            rs += __shfl_xor_sync(0xffffffffu, rs, 2);
            lr[hf] = lr[hf] * corr + rs;
#pragma unroll
            for (int dt = 0; dt < 8; dt++) {
                o[dt][2*hf]     *= corr;
                o[dt][2*hf + 1] *= corr;
            }
        }

        // ---- O += P @ V, term-major ----
#pragma unroll
        for (int kc = 0; kc < 4; kc++) {
            unsigned pah[4], pal[4];
#pragma unroll
            for (int q = 0; q < 2; q++) {
                float x0 = s[2*kc + q][0], x1 = s[2*kc + q][1];
                float x2 = s[2*kc + q][2], x3 = s[2*kc + q][3];
                float h0 = bfhi(x0), h1 = bfhi(x1);
                float h2 = bfhi(x2), h3 = bfhi(x3);
                pah[2*q]     = pk2(x0, x1);
                pah[2*q + 1] = pk2(x2, x3);
                pal[2*q]     = pk2(x0 - h0, x1 - h1);
                pal[2*q + 1] = pk2(x2 - h2, x3 - h3);
            }
            unsigned vbh[4][4], vbl[4][4];
            load_vb(sVh, sVl, kc, lane, vbh, vbl);
#pragma unroll
            for (int dtp = 0; dtp < 4; dtp++) {
                mma16816(o[2*dtp],   pah, vbh[dtp]);
                mma16816(o[2*dtp+1], pah, vbh[dtp] + 2);
            }
#pragma unroll
            for (int dtp = 0; dtp < 4; dtp++) {
                mma16816(o[2*dtp],   pah, vbl[dtp]);
                mma16816(o[2*dtp+1], pah, vbl[dtp] + 2);
            }
#pragma unroll
            for (int dtp = 0; dtp < 4; dtp++) {
                mma16816(o[2*dtp],   pal, vbh[dtp]);
                mma16816(o[2*dtp+1], pal, vbh[dtp] + 2);
            }
        }
        __syncthreads();   // all warps done reading stage t before refill
    }

    // epilogue: normalize, write segmented bf16 hi/lo to g_aoa
    const int bb = bh >> 4, h = bh & 15;
    const float inv0 = 1.f / lr[0], inv1 = 1.f / lr[1];
    const int mrow0 = q0 + warp * 16 + g;
#pragma unroll
    for (int dt = 0; dt < 8; dt++) {
        int col = h * 64 + dt * 8 + 2 * t4;
        size_t seg = (size_t)(col >> 4) * 32 + (col & 15);
        size_t i0 = ((size_t)(bb * S_ + mrow0))     * 2048 + seg;
        size_t i1 = ((size_t)(bb * S_ + mrow0 + 8)) * 2048 + seg;
        float v0 = o[dt][0] * inv0, v1 = o[dt][1] * inv0;
        float w0 = o[dt][2] * inv1, w1 = o[dt][3] * inv1;
        float h0 = bfhi(v0), h1 = bfhi(v1), e0 = bfhi(w0), e1 = bfhi(w1);
        *(unsigned*)&g_aoa[i0]      = pk2(v0, v1);
        *(unsigned*)&g_aoa[i0 + 16] = pk2(v0 - h0, v1 - h1);
        *(unsigned*)&g_aoa[i1]      = pk2(w0, w1);
        *(unsigned*)&g_aoa[i1 + 16] = pk2(w0 - e0, w1 - e1);
    }
}

// ---------------------------------------------------------------------------
extern "C" void kernel_launch(void* const* d_in, const int* in_sizes, int n_in,
                              void* d_out, int out_size)
{
    (void)in_sizes; (void)n_in; (void)out_size;
    const float* x      = (const float*)d_in[0];
    const float* W_attn = (const float*)d_in[1];
    const float* b_attn = (const float*)d_in[2];
    const float* W_proj = (const float*)d_in[3];
    const float* b_proj = (const float*)d_in[4];
    float* out = (float*)d_out;

    const int GSMEM = 3 * 32768;            // 98304
    const int FSMEM = 32768 + 2 * 32768;    // 98304
    cudaFuncSetAttribute(tc_gemm5<N3_, true>,
        cudaFuncAttributeMaxDynamicSharedMemorySize, GSMEM);
    cudaFuncSetAttribute(tc_gemm5<C_, false>,
        cudaFuncAttributeMaxDynamicSharedMemorySize, GSMEM);
    cudaFuncSetAttribute(flash_attn_tc,
        cudaFuncAttributeMaxDynamicSharedMemorySize, FSMEM);

    conv_seg_x  <<<M_*C_/16/256, 256>>>(x);
    conv_plane<0><<<C_*N3_/8/256, 256>>>(W_attn);
    conv_plane<1><<<C_*C_/8/256,  256>>>(W_proj);
    tc_gemm5<N3_, true ><<<dim3(N3_/128, M_/128), 256, GSMEM>>>(b_attn, nullptr);
    flash_attn_tc<<<dim3(S_/128, B_*H_), 256, FSMEM>>>();
    tc_gemm5<C_,  false><<<dim3(C_/128,  M_/128), 256, GSMEM>>>(b_proj, out);
}

// round 13
// speedup vs baseline: 1.0093x; 1.0093x over previous
#include <cuda_runtime.h>
#include <cuda_bf16.h>
#include <cstdint>

#define B_  4
#define S_  2048
#define C_  1024
#define H_  16
#define D_  64
#define M_  (B_*S_)     // 8192
#define N3_ (3*C_)      // 3072

// Scratch (no allocations allowed)
__device__ __align__(16) __nv_bfloat16 g_qh[B_*H_*S_*D_];
__device__ __align__(16) __nv_bfloat16 g_ql[B_*H_*S_*D_];
__device__ __align__(16) __nv_bfloat16 g_kh[B_*H_*S_*D_];
__device__ __align__(16) __nv_bfloat16 g_kl[B_*H_*S_*D_];
__device__ __align__(16) __nv_bfloat16 g_vh[B_*H_*S_*D_];
__device__ __align__(16) __nv_bfloat16 g_vl[B_*H_*S_*D_];
// A operands, segmented: per row, per 16-k group: [16 hi | 16 lo] bf16
__device__ __align__(16) __nv_bfloat16 g_xa [M_*C_*2];
__device__ __align__(16) __nv_bfloat16 g_aoa[M_*C_*2];
// Weight planes (row-major [K][N]) bf16 hi/lo
__device__ __align__(16) __nv_bfloat16 g_wah[C_*N3_], g_wal[C_*N3_];
__device__ __align__(16) __nv_bfloat16 g_wph[C_*C_],  g_wpl[C_*C_];

// ---------------------------------------------------------------------------
// helpers
// ---------------------------------------------------------------------------
__device__ __forceinline__ unsigned pk2(float a, float b) {
    __nv_bfloat162 t = __floats2bfloat162_rn(a, b);
    return *reinterpret_cast<const unsigned*>(&t);
}
__device__ __forceinline__ float bfhi(float x) {
    return __bfloat162float(__float2bfloat16_rn(x));
}
__device__ __forceinline__ void ldsm4(unsigned r[4], unsigned addr) {
    asm volatile("ldmatrix.sync.aligned.m8n8.x4.shared.b16 {%0,%1,%2,%3}, [%4];\n"
        : "=r"(r[0]), "=r"(r[1]), "=r"(r[2]), "=r"(r[3]) : "r"(addr));
}
__device__ __forceinline__ void ldsm4t(unsigned r[4], unsigned addr) {
    asm volatile("ldmatrix.sync.aligned.m8n8.x4.trans.shared.b16 {%0,%1,%2,%3}, [%4];\n"
        : "=r"(r[0]), "=r"(r[1]), "=r"(r[2]), "=r"(r[3]) : "r"(addr));
}
__device__ __forceinline__ void mma16816(float c[4], const unsigned a[4],
                                         const unsigned b[2]) {
    asm volatile(
        "mma.sync.aligned.m16n8k16.row.col.f32.bf16.bf16.f32 "
        "{%0,%1,%2,%3}, {%4,%5,%6,%7}, {%8,%9}, {%0,%1,%2,%3};\n"
        : "+f"(c[0]), "+f"(c[1]), "+f"(c[2]), "+f"(c[3])
        : "r"(a[0]), "r"(a[1]), "r"(a[2]), "r"(a[3]), "r"(b[0]), "r"(b[1]));
}
__device__ __forceinline__ void cpa16(unsigned dst, const void* src) {
    asm volatile("cp.async.cg.shared.global [%0], [%1], 16;\n"
        :: "r"(dst), "l"(__cvta_generic_to_global(src)));
}
#define CP_COMMIT() asm volatile("cp.async.commit_group;\n" ::: "memory")
#define CP_WAIT1()  asm volatile("cp.async.wait_group 1;\n" ::: "memory")
#define CP_WAIT0()  asm volatile("cp.async.wait_group 0;\n" ::: "memory")

// ---------------------------------------------------------------------------
// Conversion kernels (memory-bound, run once)
// ---------------------------------------------------------------------------
__global__ __launch_bounds__(256) void conv_seg_x(const float* __restrict__ src)
{
    size_t s = (size_t)blockIdx.x * 256 + threadIdx.x;   // 16-elem segment id
    const float4* p = (const float4*)(src + s * 16);
    float4 a = p[0], b = p[1], c = p[2], d = p[3];
    __nv_bfloat16* dst = g_xa + s * 32;
    uint4 u;
    u.x = pk2(a.x, a.y); u.y = pk2(a.z, a.w);
    u.z = pk2(b.x, b.y); u.w = pk2(b.z, b.w);
    *(uint4*)dst = u;
    u.x = pk2(a.x - bfhi(a.x), a.y - bfhi(a.y));
    u.y = pk2(a.z - bfhi(a.z), a.w - bfhi(a.w));
    u.z = pk2(b.x - bfhi(b.x), b.y - bfhi(b.y));
    u.w = pk2(b.z - bfhi(b.z), b.w - bfhi(b.w));
    *(uint4*)(dst + 16) = u;
    u.x = pk2(c.x, c.y); u.y = pk2(c.z, c.w);
    u.z = pk2(d.x, d.y); u.w = pk2(d.z, d.w);
    *(uint4*)(dst + 8) = u;
    u.x = pk2(c.x - bfhi(c.x), c.y - bfhi(c.y));
    u.y = pk2(c.z - bfhi(c.z), c.w - bfhi(c.w));
    u.z = pk2(d.x - bfhi(d.x), d.y - bfhi(d.y));
    u.w = pk2(d.z - bfhi(d.z), d.w - bfhi(d.w));
    *(uint4*)(dst + 24) = u;
}

template<int P>   // 0 = W_attn, 1 = W_proj
__global__ __launch_bounds__(256) void conv_plane(const float* __restrict__ src)
{
    size_t i = ((size_t)blockIdx.x * 256 + threadIdx.x) * 8;
    const float4* p = (const float4*)(src + i);
    float4 a = p[0], b = p[1];
    __nv_bfloat16* dh = (P == 0) ? g_wah : g_wph;
    __nv_bfloat16* dl = (P == 0) ? g_wal : g_wpl;
    uint4 u;
    u.x = pk2(a.x, a.y); u.y = pk2(a.z, a.w);
    u.z = pk2(b.x, b.y); u.w = pk2(b.z, b.w);
    *(uint4*)(dh + i) = u;
    u.x = pk2(a.x - bfhi(a.x), a.y - bfhi(a.y));
    u.y = pk2(a.z - bfhi(a.z), a.w - bfhi(a.w));
    u.z = pk2(b.x - bfhi(b.x), b.y - bfhi(b.y));
    u.w = pk2(b.z - bfhi(b.z), b.w - bfhi(b.w));
    *(uint4*)(dl + i) = u;
}

// ---------------------------------------------------------------------------
// PERSISTENT tensor-core GEMM, bf16 hi/lo, BK=32 stages (32KB x 3 = 96KB).
// 296 CTAs (148 SMs x 2 resident) grid-stride over output tiles: no wave
// quantization. Inner loop identical to R10's proven tc_gemm5.
// ---------------------------------------------------------------------------
template<int LDB, bool SCATTER>
__global__ __launch_bounds__(256, 2) void tc_gemm6(
    const float* __restrict__ bias, float* __restrict__ out)
{
    extern __shared__ __align__(16) unsigned char smem[];
    const unsigned sb = (unsigned)__cvta_generic_to_shared(smem);
    const __nv_bfloat16* Aseg = SCATTER ? g_xa  : g_aoa;
    const __nv_bfloat16* Whp  = SCATTER ? g_wah : g_wph;
    const __nv_bfloat16* Wlp  = SCATTER ? g_wal : g_wpl;

    const int tid = threadIdx.x, lane = tid & 31, warp = tid >> 5;
    const int mw = warp & 1, nw = warp >> 1;

    const int ar = tid >> 3, ac = tid & 7;
    const unsigned aDst0 = ar * 128 + ((ac ^ (ar & 7)) << 4);
    const int bk = tid >> 4, bn = tid & 15;
    const unsigned bDst0 = 16384 + bk * 256 + ((bn ^ (bk & 7)) << 4);
    const size_t bHalf = (size_t)16 * LDB * 2;
    const size_t bStep = (size_t)32 * LDB * 2;

    const int NTN = LDB / 128;                 // n tiles
    const int NT  = NTN * (M_ / 128);          // total tiles

    for (int tile = blockIdx.x; tile < NT; tile += gridDim.x) {
        const int n0 = (tile % NTN) << 7;
        const int m0 = (tile / NTN) << 7;

        const char* aSrc0 = (const char*)Aseg + (size_t)(m0 + ar) * 4096 + ac * 16;
        const char* bSrcH = (const char*)Whp + ((size_t)bk * LDB + n0 + bn * 8) * 2;
        const char* bSrcL = (const char*)Wlp + ((size_t)bk * LDB + n0 + bn * 8) * 2;

        float acc[16][4];
#pragma unroll
        for (int i = 0; i < 16; i++)
#pragma unroll
            for (int j = 0; j < 4; j++) acc[i][j] = 0.f;

        auto issue = [&](int kt) {
            unsigned st = sb + (kt % 3) * 32768;
            const char* as = aSrc0 + (size_t)kt * 128;
#pragma unroll
            for (int i = 0; i < 4; i++)
                cpa16(st + aDst0 + i * 4096, as + (size_t)i * 131072);
            const char* bs = bSrcH + (size_t)kt * bStep;
            cpa16(st + bDst0,        bs);
            cpa16(st + bDst0 + 4096, bs + bHalf);
            const char* bl_ = bSrcL + (size_t)kt * bStep;
            cpa16(st + bDst0 + 8192,        bl_);
            cpa16(st + bDst0 + 8192 + 4096, bl_ + bHalf);
        };

        __syncthreads();   // protect smem stages from previous tile's readers
        issue(0); CP_COMMIT();
        issue(1); CP_COMMIT();

        const int KT = C_ / 32;   // 32
        for (int kt = 0; kt < KT; kt++) {
            CP_WAIT1();
            __syncthreads();
            if (kt + 2 < KT) issue(kt + 2);
            CP_COMMIT();

            const unsigned sA  = sb + (kt % 3) * 32768;
            const unsigned sBh = sA + 16384, sBl = sA + 24576;

#pragma unroll
            for (int kc = 0; kc < 2; kc++) {
                unsigned ah[4][4], al[4][4], bh[2][4], bl[2][4];
#pragma unroll
                for (int mt = 0; mt < 4; mt++) {
                    int row = mw * 64 + mt * 16 + (lane & 15);
                    unsigned b128 = sA + row * 128;
                    int chH = kc * 4 + (lane >> 4);
                    int chL = kc * 4 + 2 + (lane >> 4);
                    ldsm4(ah[mt], b128 + ((chH ^ (row & 7)) << 4));
                    ldsm4(al[mt], b128 + ((chL ^ (row & 7)) << 4));
                }
#pragma unroll
                for (int tp = 0; tp < 2; tp++) {
                    int k  = kc * 16 + (lane & 15);
                    int nc = nw * 4 + tp * 2 + (lane >> 4);
                    unsigned off = k * 256 + ((nc ^ (k & 7)) << 4);
                    ldsm4t(bh[tp], sBh + off);
                    ldsm4t(bl[tp], sBl + off);
                }
#pragma unroll
                for (int mt = 0; mt < 4; mt++)
#pragma unroll
                    for (int tp = 0; tp < 2; tp++)
#pragma unroll
                        for (int hf = 0; hf < 2; hf++)
                            mma16816(acc[mt*4 + tp*2 + hf], ah[mt], bh[tp] + hf*2);
#pragma unroll
                for (int mt = 0; mt < 4; mt++)
#pragma unroll
                    for (int tp = 0; tp < 2; tp++)
#pragma unroll
                        for (int hf = 0; hf < 2; hf++)
                            mma16816(acc[mt*4 + tp*2 + hf], ah[mt], bl[tp] + hf*2);
#pragma unroll
                for (int mt = 0; mt < 4; mt++)
#pragma unroll
                    for (int tp = 0; tp < 2; tp++)
#pragma unroll
                        for (int hf = 0; hf < 2; hf++)
                            mma16816(acc[mt*4 + tp*2 + hf], al[mt], bh[tp] + hf*2);
            }
        }

        // Epilogue. Fragment: c0,c1 -> row g, cols cp..; c2,c3 -> row g+8.
        const int g  = lane >> 2;
        const int cp = (lane & 3) << 1;
        if (SCATTER) {
            const int part = n0 >> 10;
            __nv_bfloat16* dH = (part == 0) ? g_qh : (part == 1) ? g_kh : g_vh;
            __nv_bfloat16* dL = (part == 0) ? g_ql : (part == 1) ? g_kl : g_vl;
            const float fs = (part == 0) ? 0.125f : 1.0f;
#pragma unroll
            for (int mt = 0; mt < 4; mt++) {
#pragma unroll
                for (int nt = 0; nt < 4; nt++) {
                    int n = n0 + nw * 32 + nt * 8 + cp;
                    int c = n & (C_ - 1);
                    int hh = c >> 6, d = c & 63;
                    float b0 = bias[n], b1 = bias[n + 1];
                    float* a4 = acc[mt * 4 + nt];
#pragma unroll
                    for (int rr = 0; rr < 2; rr++) {
                        int m  = m0 + mw * 64 + mt * 16 + g + rr * 8;
                        int bb = m >> 11, ss = m & (S_ - 1);
                        float v0 = (a4[rr * 2] + b0) * fs;
                        float v1 = (a4[rr * 2 + 1] + b1) * fs;
                        float h0 = bfhi(v0), h1 = bfhi(v1);
                        size_t idx = (((size_t)(bb * H_ + hh)) * S_ + ss) * D_ + d;
                        *(unsigned*)&dH[idx] = pk2(v0, v1);
                        *(unsigned*)&dL[idx] = pk2(v0 - h0, v1 - h1);
                    }
                }
            }
        } else {
#pragma unroll
            for (int mt = 0; mt < 4; mt++) {
#pragma unroll
                for (int nt = 0; nt < 4; nt++) {
                    int n = n0 + nw * 32 + nt * 8 + cp;
                    float b0 = bias[n], b1 = bias[n + 1];
                    float* a4 = acc[mt * 4 + nt];
#pragma unroll
                    for (int rr = 0; rr < 2; rr++) {
                        int m = m0 + mw * 64 + mt * 16 + g + rr * 8;
                        float2 o = make_float2(a4[rr * 2] + b0,
                                               a4[rr * 2 + 1] + b1);
                        *(float2*)&out[(size_t)m * C_ + n] = o;
                    }
                }
            }
        }
    }
}

// ---------------------------------------------------------------------------
// Flash attention fragment-load helpers
// ---------------------------------------------------------------------------
__device__ __forceinline__ void load_kb(unsigned sKh, unsigned sKl, int kc, int lane,
                                        unsigned kbh[4][4], unsigned kbl[4][4]) {
#pragma unroll
    for (int ntp = 0; ntp < 4; ntp++) {
        int kr = ntp * 16 + ((lane >> 4) << 3) + (lane & 7);
        unsigned koff = kr * 128 +
            (((unsigned)((2 * kc + ((lane >> 3) & 1)) ^ (kr & 7))) << 4);
        ldsm4(kbh[ntp], sKh + koff);
        ldsm4(kbl[ntp], sKl + koff);
    }
}
__device__ __forceinline__ void load_vb(unsigned sVh, unsigned sVl, int kc, int lane,
                                        unsigned vbh[4][4], unsigned vbl[4][4]) {
#pragma unroll
    for (int dtp = 0; dtp < 4; dtp++) {
        int vr = kc * 16 + (lane & 15);
        unsigned voff = vr * 128 +
            (((unsigned)((2 * dtp + (lane >> 4)) ^ (vr & 7))) << 4);
        ldsm4t(vbh[dtp], sVh + voff);
        ldsm4t(vbl[dtp], sVl + voff);
    }
}

// ---------------------------------------------------------------------------
// Tensor-core flash attention — EXACT R10 version (known-good at 772us).
// 128 threads (4 warps), 64 queries, 64-key tiles, D=64.
// cp.async double-buffered K/V tiles (2 x 32KB) + Q 16KB = 80KB dynamic smem.
// ---------------------------------------------------------------------------
__global__ __launch_bounds__(128) void flash_attn_tc()
{
    extern __shared__ __align__(16) unsigned char fsm[];
    const unsigned sb = (unsigned)__cvta_generic_to_shared(fsm);
    const unsigned sQh = sb, sQl = sb + 8192;

    const int tid  = threadIdx.x;
    const int lane = tid & 31, warp = tid >> 5;
    const int bh = blockIdx.y;
    const int q0 = blockIdx.x << 6;
    const size_t base = (size_t)bh * (S_ * D_);
    const int g = lane >> 2, t4 = lane & 3;

#pragma unroll
    for (int i = 0; i < 4; i++) {
        int f = i * 128 + tid;
        int r = f >> 3, ch = f & 7;
        unsigned off = r * 128 + (((unsigned)(ch ^ (r & 7))) << 4);
        size_t src = base + (size_t)(q0 + r) * 64 + ch * 8;
        *(uint4*)(fsm + off)        = *(const uint4*)(g_qh + src);
        *(uint4*)(fsm + 8192 + off) = *(const uint4*)(g_ql + src);
    }

    auto issueKV = [&](int t) {
        unsigned stg = sb + 16384 + (t & 1) * 32768;
        size_t rowb = base + (size_t)(t << 6) * 64;
        const __nv_bfloat16* s0 = g_kh + rowb;
        const __nv_bfloat16* s1 = g_kl + rowb;
        const __nv_bfloat16* s2 = g_vh + rowb;
        const __nv_bfloat16* s3 = g_vl + rowb;
#pragma unroll
        for (int i = 0; i < 16; i++) {
            int arr = i >> 2;
            int rem = (i & 3) * 128 + tid;
            int r = rem >> 3, ch = rem & 7;
            const __nv_bfloat16* sp = (arr == 0) ? s0 : (arr == 1) ? s1
                                     : (arr == 2) ? s2 : s3;
            cpa16(stg + arr * 8192 + r * 128 + ((ch ^ (r & 7)) << 4),
                  sp + (size_t)r * 64 + ch * 8);
        }
    };

    float o[8][4];
#pragma unroll
    for (int i = 0; i < 8; i++)
#pragma unroll
        for (int j = 0; j < 4; j++) o[i][j] = 0.f;
    float mr[2] = {-1e30f, -1e30f}, lr[2] = {0.f, 0.f};

    const int ntiles = blockIdx.x + 1;
    issueKV(0); CP_COMMIT();

    for (int t = 0; t < ntiles; t++) {
        if (t + 1 < ntiles) { issueKV(t + 1); CP_COMMIT(); CP_WAIT1(); }
        else                { CP_WAIT0(); }
        __syncthreads();

        const unsigned stg = sb + 16384 + (t & 1) * 32768;
        const unsigned sKh = stg, sKl = stg + 8192;
        const unsigned sVh = stg + 16384, sVl = stg + 24576;

        float s[8][4];
#pragma unroll
        for (int i = 0; i < 8; i++)
#pragma unroll
            for (int j = 0; j < 4; j++) s[i][j] = 0.f;

        unsigned kbh[2][4][4], kbl[2][4][4];
        load_kb(sKh, sKl, 0, lane, kbh[0], kbl[0]);
#pragma unroll
        for (int kc = 0; kc < 4; kc++) {
            unsigned ah[4], al[4];
            int qr = warp * 16 + (lane & 15);
            unsigned qoff = qr * 128 +
                (((unsigned)((2 * kc + (lane >> 4)) ^ (qr & 7))) << 4);
            ldsm4(ah, sQh + qoff);
            ldsm4(al, sQl + qoff);
            if (kc < 3)
                load_kb(sKh, sKl, kc + 1, lane, kbh[(kc + 1) & 1], kbl[(kc + 1) & 1]);
            const int b = kc & 1;
#pragma unroll
            for (int ntp = 0; ntp < 4; ntp++) {
                mma16816(s[2*ntp],   ah, kbh[b][ntp]);
                mma16816(s[2*ntp+1], ah, kbh[b][ntp] + 2);
            }
#pragma unroll
            for (int ntp = 0; ntp < 4; ntp++) {
                mma16816(s[2*ntp],   ah, kbl[b][ntp]);
                mma16816(s[2*ntp+1], ah, kbl[b][ntp] + 2);
            }
#pragma unroll
            for (int ntp = 0; ntp < 4; ntp++) {
                mma16816(s[2*ntp],   al, kbh[b][ntp]);
                mma16816(s[2*ntp+1], al, kbh[b][ntp] + 2);
            }
        }

        if (t == ntiles - 1) {
            int row_lo = warp * 16 + g;
            int row_hi = row_lo + 8;
#pragma unroll
            for (int nt = 0; nt < 8; nt++) {
#pragma unroll
                for (int j = 0; j < 2; j++) {
                    int col = nt * 8 + 2 * t4 + j;
                    if (col > row_lo) s[nt][j]     = -1e30f;
                    if (col > row_hi) s[nt][2 + j] = -1e30f;
                }
            }
        }

#pragma unroll
        for (int hf = 0; hf < 2; hf++) {
            float mx = -1e30f;
#pragma unroll
            for (int nt = 0; nt < 8; nt++)
                mx = fmaxf(mx, fmaxf(s[nt][2*hf], s[nt][2*hf+1]));
            mx = fmaxf(mx, __shfl_xor_sync(0xffffffffu, mx, 1));
            mx = fmaxf(mx, __shfl_xor_sync(0xffffffffu, mx, 2));
            float mn   = fmaxf(mr[hf], mx);
            float corr = __expf(mr[hf] - mn);
            mr[hf] = mn;
            float rs = 0.f;
#pragma unroll
            for (int nt = 0; nt < 8; nt++) {
                float p0 = __expf(s[nt][2*hf]     - mn);
                float p1 = __expf(s[nt][2*hf + 1] - mn);
                s[nt][2*hf] = p0; s[nt][2*hf+1] = p1;
                rs += p0 + p1;
            }
            rs += __shfl_xor_sync(0xffffffffu, rs, 1);
            rs += __shfl_xor_sync(0xffffffffu, rs, 2);
            lr[hf] = lr[hf] * corr + rs;
#pragma unroll
            for (int dt = 0; dt < 8; dt++) {
                o[dt][2*hf]     *= corr;
                o[dt][2*hf + 1] *= corr;
            }
        }

        unsigned vbh[2][4][4], vbl[2][4][4];
        load_vb(sVh, sVl, 0, lane, vbh[0], vbl[0]);
#pragma unroll
        for (int kc = 0; kc < 4; kc++) {
            unsigned pah[4], pal[4];
#pragma unroll
            for (int q = 0; q < 2; q++) {
                float x0 = s[2*kc + q][0], x1 = s[2*kc + q][1];
                float x2 = s[2*kc + q][2], x3 = s[2*kc + q][3];
                float h0 = bfhi(x0), h1 = bfhi(x1);
                float h2 = bfhi(x2), h3 = bfhi(x3);
                pah[2*q]     = pk2(x0, x1);
                pah[2*q + 1] = pk2(x2, x3);
                pal[2*q]     = pk2(x0 - h0, x1 - h1);
                pal[2*q + 1] = pk2(x2 - h2, x3 - h3);
            }
            if (kc < 3)
                load_vb(sVh, sVl, kc + 1, lane, vbh[(kc + 1) & 1], vbl[(kc + 1) & 1]);
            const int b = kc & 1;
#pragma unroll
            for (int dtp = 0; dtp < 4; dtp++) {
                mma16816(o[2*dtp],   pah, vbh[b][dtp]);
                mma16816(o[2*dtp+1], pah, vbh[b][dtp] + 2);
            }
#pragma unroll
            for (int dtp = 0; dtp < 4; dtp++) {
                mma16816(o[2*dtp],   pah, vbl[b][dtp]);
                mma16816(o[2*dtp+1], pah, vbl[b][dtp] + 2);
            }
#pragma unroll
            for (int dtp = 0; dtp < 4; dtp++) {
                mma16816(o[2*dtp],   pal, vbh[b][dtp]);
                mma16816(o[2*dtp+1], pal, vbh[b][dtp] + 2);
            }
        }
        __syncthreads();
    }

    const int bb = bh >> 4, h = bh & 15;
    const float inv0 = 1.f / lr[0], inv1 = 1.f / lr[1];
    const int mrow0 = q0 + warp * 16 + g;
#pragma unroll
    for (int dt = 0; dt < 8; dt++) {
        int col = h * 64 + dt * 8 + 2 * t4;
        size_t seg = (size_t)(col >> 4) * 32 + (col & 15);
        size_t i0 = ((size_t)(bb * S_ + mrow0))     * 2048 + seg;
        size_t i1 = ((size_t)(bb * S_ + mrow0 + 8)) * 2048 + seg;
        float v0 = o[dt][0] * inv0, v1 = o[dt][1] * inv0;
        float w0 = o[dt][2] * inv1, w1 = o[dt][3] * inv1;
        float h0 = bfhi(v0), h1 = bfhi(v1), e0 = bfhi(w0), e1 = bfhi(w1);
        *(unsigned*)&g_aoa[i0]      = pk2(v0, v1);
        *(unsigned*)&g_aoa[i0 + 16] = pk2(v0 - h0, v1 - h1);
        *(unsigned*)&g_aoa[i1]      = pk2(w0, w1);
        *(unsigned*)&g_aoa[i1 + 16] = pk2(w0 - e0, w1 - e1);
    }
}

// ---------------------------------------------------------------------------
extern "C" void kernel_launch(void* const* d_in, const int* in_sizes, int n_in,
                              void* d_out, int out_size)
{
    (void)in_sizes; (void)n_in; (void)out_size;
    const float* x      = (const float*)d_in[0];
    const float* W_attn = (const float*)d_in[1];
    const float* b_attn = (const float*)d_in[2];
    const float* W_proj = (const float*)d_in[3];
    const float* b_proj = (const float*)d_in[4];
    float* out = (float*)d_out;

    const int GSMEM = 3 * 32768;            // 98304
    const int FSMEM = 16384 + 2 * 32768;    // 81920
    const int NCTA  = 148 * 2;              // persistent: all resident
    cudaFuncSetAttribute(tc_gemm6<N3_, true>,
        cudaFuncAttributeMaxDynamicSharedMemorySize, GSMEM);
    cudaFuncSetAttribute(tc_gemm6<C_, false>,
        cudaFuncAttributeMaxDynamicSharedMemorySize, GSMEM);
    cudaFuncSetAttribute(flash_attn_tc,
        cudaFuncAttributeMaxDynamicSharedMemorySize, FSMEM);

    conv_seg_x  <<<M_*C_/16/256, 256>>>(x);
    conv_plane<0><<<C_*N3_/8/256, 256>>>(W_attn);
    conv_plane<1><<<C_*C_/8/256,  256>>>(W_proj);
    tc_gemm6<N3_, true ><<<NCTA, 256, GSMEM>>>(b_attn, nullptr);
    flash_attn_tc<<<dim3(S_/64, B_*H_), 128, FSMEM>>>();
    tc_gemm6<C_,  false><<<NCTA, 256, GSMEM>>>(b_proj, out);
}

// round 14
// speedup vs baseline: 1.0511x; 1.0414x over previous
#include <cuda_runtime.h>
#include <cuda_bf16.h>
#include <cstdint>

#define B_  4
#define S_  2048
#define C_  1024
#define H_  16
#define D_  64
#define M_  (B_*S_)     // 8192
#define N3_ (3*C_)      // 3072

// Scratch (no allocations allowed)
__device__ __align__(16) __nv_bfloat16 g_qh[B_*H_*S_*D_];
__device__ __align__(16) __nv_bfloat16 g_ql[B_*H_*S_*D_];
__device__ __align__(16) __nv_bfloat16 g_kh[B_*H_*S_*D_];
__device__ __align__(16) __nv_bfloat16 g_kl[B_*H_*S_*D_];
__device__ __align__(16) __nv_bfloat16 g_vh[B_*H_*S_*D_];
__device__ __align__(16) __nv_bfloat16 g_vl[B_*H_*S_*D_];
// A operands, segmented: per row, per 16-k group: [16 hi | 16 lo] bf16
__device__ __align__(16) __nv_bfloat16 g_xa [M_*C_*2];
__device__ __align__(16) __nv_bfloat16 g_aoa[M_*C_*2];
// Weight planes (row-major [K][N]) bf16 hi/lo
__device__ __align__(16) __nv_bfloat16 g_wah[C_*N3_], g_wal[C_*N3_];
__device__ __align__(16) __nv_bfloat16 g_wph[C_*C_],  g_wpl[C_*C_];

// ---------------------------------------------------------------------------
// helpers
// ---------------------------------------------------------------------------
__device__ __forceinline__ unsigned pk2(float a, float b) {
    __nv_bfloat162 t = __floats2bfloat162_rn(a, b);
    return *reinterpret_cast<const unsigned*>(&t);
}
__device__ __forceinline__ float bfhi(float x) {
    return __bfloat162float(__float2bfloat16_rn(x));
}
__device__ __forceinline__ void ldsm4(unsigned r[4], unsigned addr) {
    asm volatile("ldmatrix.sync.aligned.m8n8.x4.shared.b16 {%0,%1,%2,%3}, [%4];\n"
        : "=r"(r[0]), "=r"(r[1]), "=r"(r[2]), "=r"(r[3]) : "r"(addr));
}
__device__ __forceinline__ void ldsm4t(unsigned r[4], unsigned addr) {
    asm volatile("ldmatrix.sync.aligned.m8n8.x4.trans.shared.b16 {%0,%1,%2,%3}, [%4];\n"
        : "=r"(r[0]), "=r"(r[1]), "=r"(r[2]), "=r"(r[3]) : "r"(addr));
}
__device__ __forceinline__ void mma16816(float c[4], const unsigned a[4],
                                         const unsigned b[2]) {
    asm volatile(
        "mma.sync.aligned.m16n8k16.row.col.f32.bf16.bf16.f32 "
        "{%0,%1,%2,%3}, {%4,%5,%6,%7}, {%8,%9}, {%0,%1,%2,%3};\n"
        : "+f"(c[0]), "+f"(c[1]), "+f"(c[2]), "+f"(c[3])
        : "r"(a[0]), "r"(a[1]), "r"(a[2]), "r"(a[3]), "r"(b[0]), "r"(b[1]));
}
__device__ __forceinline__ void cpa16(unsigned dst, const void* src) {
    asm volatile("cp.async.cg.shared.global [%0], [%1], 16;\n"
        :: "r"(dst), "l"(__cvta_generic_to_global(src)));
}
#define CP_COMMIT() asm volatile("cp.async.commit_group;\n" ::: "memory")
#define CP_WAIT1()  asm volatile("cp.async.wait_group 1;\n" ::: "memory")
#define CP_WAIT0()  asm volatile("cp.async.wait_group 0;\n" ::: "memory")

// ---------------------------------------------------------------------------
// Conversion kernels (memory-bound, run once)
// ---------------------------------------------------------------------------
__global__ __launch_bounds__(256) void conv_seg_x(const float* __restrict__ src)
{
    size_t s = (size_t)blockIdx.x * 256 + threadIdx.x;   // 16-elem segment id
    const float4* p = (const float4*)(src + s * 16);
    float4 a = p[0], b = p[1], c = p[2], d = p[3];
    __nv_bfloat16* dst = g_xa + s * 32;
    uint4 u;
    u.x = pk2(a.x, a.y); u.y = pk2(a.z, a.w);
    u.z = pk2(b.x, b.y); u.w = pk2(b.z, b.w);
    *(uint4*)dst = u;
    u.x = pk2(a.x - bfhi(a.x), a.y - bfhi(a.y));
    u.y = pk2(a.z - bfhi(a.z), a.w - bfhi(a.w));
    u.z = pk2(b.x - bfhi(b.x), b.y - bfhi(b.y));
    u.w = pk2(b.z - bfhi(b.z), b.w - bfhi(b.w));
    *(uint4*)(dst + 16) = u;
    u.x = pk2(c.x, c.y); u.y = pk2(c.z, c.w);
    u.z = pk2(d.x, d.y); u.w = pk2(d.z, d.w);
    *(uint4*)(dst + 8) = u;
    u.x = pk2(c.x - bfhi(c.x), c.y - bfhi(c.y));
    u.y = pk2(c.z - bfhi(c.z), c.w - bfhi(c.w));
    u.z = pk2(d.x - bfhi(d.x), d.y - bfhi(d.y));
    u.w = pk2(d.z - bfhi(d.z), d.w - bfhi(d.w));
    *(uint4*)(dst + 24) = u;
}

template<int P>   // 0 = W_attn, 1 = W_proj
__global__ __launch_bounds__(256) void conv_plane(const float* __restrict__ src)
{
    size_t i = ((size_t)blockIdx.x * 256 + threadIdx.x) * 8;
    const float4* p = (const float4*)(src + i);
    float4 a = p[0], b = p[1];
    __nv_bfloat16* dh = (P == 0) ? g_wah : g_wph;
    __nv_bfloat16* dl = (P == 0) ? g_wal : g_wpl;
    uint4 u;
    u.x = pk2(a.x, a.y); u.y = pk2(a.z, a.w);
    u.z = pk2(b.x, b.y); u.w = pk2(b.z, b.w);
    *(uint4*)(dh + i) = u;
    u.x = pk2(a.x - bfhi(a.x), a.y - bfhi(a.y));
    u.y = pk2(a.z - bfhi(a.z), a.w - bfhi(a.w));
    u.z = pk2(b.x - bfhi(b.x), b.y - bfhi(b.y));
    u.w = pk2(b.z - bfhi(b.z), b.w - bfhi(b.w));
    *(uint4*)(dl + i) = u;
}

// ---------------------------------------------------------------------------
// Tensor-core GEMM — EXACT R10 version (proven 337us / tensor 75.7%).
// bf16 hi/lo, BK=32 stages (32KB x 3 = 96KB dynamic smem),
// __launch_bounds__(256, 2): two CTAs per SM break barrier phase lock.
// ---------------------------------------------------------------------------
template<int LDB, bool SCATTER>
__global__ __launch_bounds__(256, 2) void tc_gemm5(
    const float* __restrict__ bias, float* __restrict__ out)
{
    extern __shared__ __align__(16) unsigned char smem[];
    const unsigned sb = (unsigned)__cvta_generic_to_shared(smem);
    const __nv_bfloat16* Aseg = SCATTER ? g_xa  : g_aoa;
    const __nv_bfloat16* Whp  = SCATTER ? g_wah : g_wph;
    const __nv_bfloat16* Wlp  = SCATTER ? g_wal : g_wpl;

    const int tid = threadIdx.x, lane = tid & 31, warp = tid >> 5;
    const int mw = warp & 1, nw = warp >> 1;
    const int m0 = blockIdx.y << 7, n0 = blockIdx.x << 7;

    const int ar = tid >> 3, ac = tid & 7;
    const char* aSrc0 = (const char*)Aseg + (size_t)(m0 + ar) * 4096 + ac * 16;
    const unsigned aDst0 = ar * 128 + ((ac ^ (ar & 7)) << 4);
    const int bk = tid >> 4, bn = tid & 15;
    const char* bSrcH = (const char*)Whp + ((size_t)bk * LDB + n0 + bn * 8) * 2;
    const char* bSrcL = (const char*)Wlp + ((size_t)bk * LDB + n0 + bn * 8) * 2;
    const unsigned bDst0 = 16384 + bk * 256 + ((bn ^ (bk & 7)) << 4);
    const size_t bHalf = (size_t)16 * LDB * 2;
    const size_t bStep = (size_t)32 * LDB * 2;

    float acc[16][4];
#pragma unroll
    for (int i = 0; i < 16; i++)
#pragma unroll
        for (int j = 0; j < 4; j++) acc[i][j] = 0.f;

    auto issue = [&](int kt) {
        unsigned st = sb + (kt % 3) * 32768;
        const char* as = aSrc0 + (size_t)kt * 128;
#pragma unroll
        for (int i = 0; i < 4; i++)
            cpa16(st + aDst0 + i * 4096, as + (size_t)i * 131072);
        const char* bs = bSrcH + (size_t)kt * bStep;
        cpa16(st + bDst0,        bs);
        cpa16(st + bDst0 + 4096, bs + bHalf);
        const char* bl_ = bSrcL + (size_t)kt * bStep;
        cpa16(st + bDst0 + 8192,        bl_);
        cpa16(st + bDst0 + 8192 + 4096, bl_ + bHalf);
    };

    issue(0); CP_COMMIT();
    issue(1); CP_COMMIT();

    const int KT = C_ / 32;   // 32
    for (int kt = 0; kt < KT; kt++) {
        CP_WAIT1();
        __syncthreads();
        if (kt + 2 < KT) issue(kt + 2);
        CP_COMMIT();

        const unsigned sA  = sb + (kt % 3) * 32768;
        const unsigned sBh = sA + 16384, sBl = sA + 24576;

#pragma unroll
        for (int kc = 0; kc < 2; kc++) {
            unsigned ah[4][4], al[4][4], bh[2][4], bl[2][4];
#pragma unroll
            for (int mt = 0; mt < 4; mt++) {
                int row = mw * 64 + mt * 16 + (lane & 15);
                unsigned b128 = sA + row * 128;
                int chH = kc * 4 + (lane >> 4);
                int chL = kc * 4 + 2 + (lane >> 4);
                ldsm4(ah[mt], b128 + ((chH ^ (row & 7)) << 4));
                ldsm4(al[mt], b128 + ((chL ^ (row & 7)) << 4));
            }
#pragma unroll
            for (int tp = 0; tp < 2; tp++) {
                int k  = kc * 16 + (lane & 15);
                int nc = nw * 4 + tp * 2 + (lane >> 4);
                unsigned off = k * 256 + ((nc ^ (k & 7)) << 4);
                ldsm4t(bh[tp], sBh + off);
                ldsm4t(bl[tp], sBl + off);
            }
#pragma unroll
            for (int mt = 0; mt < 4; mt++)
#pragma unroll
                for (int tp = 0; tp < 2; tp++)
#pragma unroll
                    for (int hf = 0; hf < 2; hf++)
                        mma16816(acc[mt*4 + tp*2 + hf], ah[mt], bh[tp] + hf*2);
#pragma unroll
            for (int mt = 0; mt < 4; mt++)
#pragma unroll
                for (int tp = 0; tp < 2; tp++)
#pragma unroll
                    for (int hf = 0; hf < 2; hf++)
                        mma16816(acc[mt*4 + tp*2 + hf], ah[mt], bl[tp] + hf*2);
#pragma unroll
            for (int mt = 0; mt < 4; mt++)
#pragma unroll
                for (int tp = 0; tp < 2; tp++)
#pragma unroll
                    for (int hf = 0; hf < 2; hf++)
                        mma16816(acc[mt*4 + tp*2 + hf], al[mt], bh[tp] + hf*2);
        }
    }

    const int g  = lane >> 2;
    const int cp = (lane & 3) << 1;
    if (SCATTER) {
        const int part = n0 >> 10;
        __nv_bfloat16* dH = (part == 0) ? g_qh : (part == 1) ? g_kh : g_vh;
        __nv_bfloat16* dL = (part == 0) ? g_ql : (part == 1) ? g_kl : g_vl;
        const float fs = (part == 0) ? 0.125f : 1.0f;
#pragma unroll
        for (int mt = 0; mt < 4; mt++) {
#pragma unroll
            for (int nt = 0; nt < 4; nt++) {
                int n = n0 + nw * 32 + nt * 8 + cp;
                int c = n & (C_ - 1);
                int hh = c >> 6, d = c & 63;
                float b0 = bias[n], b1 = bias[n + 1];
                float* a4 = acc[mt * 4 + nt];
#pragma unroll
                for (int rr = 0; rr < 2; rr++) {
                    int m  = m0 + mw * 64 + mt * 16 + g + rr * 8;
                    int bb = m >> 11, ss = m & (S_ - 1);
                    float v0 = (a4[rr * 2] + b0) * fs;
                    float v1 = (a4[rr * 2 + 1] + b1) * fs;
                    float h0 = bfhi(v0), h1 = bfhi(v1);
                    size_t idx = (((size_t)(bb * H_ + hh)) * S_ + ss) * D_ + d;
                    *(unsigned*)&dH[idx] = pk2(v0, v1);
                    *(unsigned*)&dL[idx] = pk2(v0 - h0, v1 - h1);
                }
            }
        }
    } else {
#pragma unroll
        for (int mt = 0; mt < 4; mt++) {
#pragma unroll
            for (int nt = 0; nt < 4; nt++) {
                int n = n0 + nw * 32 + nt * 8 + cp;
                float b0 = bias[n], b1 = bias[n + 1];
                float* a4 = acc[mt * 4 + nt];
#pragma unroll
                for (int rr = 0; rr < 2; rr++) {
                    int m = m0 + mw * 64 + mt * 16 + g + rr * 8;
                    float2 o = make_float2(a4[rr * 2] + b0, a4[rr * 2 + 1] + b1);
                    *(float2*)&out[(size_t)m * C_ + n] = o;
                }
            }
        }
    }
}

// ---------------------------------------------------------------------------
// Tensor-core flash attention v3: Q held in REGISTERS (loaded once via a
// smem bounce), smem = 2 x 32KB KV ring only -> 3 CTAs/SM. Single-buffered
// K/V fragments with hi->lo register recycling to fit 170 regs.
// 128 threads (4 warps), 64 queries, 64-key tiles, D=64.
// ---------------------------------------------------------------------------
__global__ __launch_bounds__(128, 3) void flash_attn_tc()
{
    extern __shared__ __align__(16) unsigned char fsm[];
    const unsigned sb = (unsigned)__cvta_generic_to_shared(fsm);

    const int tid  = threadIdx.x;
    const int lane = tid & 31, warp = tid >> 5;
    const int bh = blockIdx.y;
    const int q0 = blockIdx.x << 6;
    const size_t base = (size_t)bh * (S_ * D_);
    const int g = lane >> 2, t4 = lane & 3;

    // ---- one-time Q load: bounce through stage-0 smem, ldsm to registers --
#pragma unroll
    for (int i = 0; i < 4; i++) {
        int f = i * 128 + tid;
        int r = f >> 3, ch = f & 7;
        unsigned off = r * 128 + (((unsigned)(ch ^ (r & 7))) << 4);
        size_t src = base + (size_t)(q0 + r) * 64 + ch * 8;
        *(uint4*)(fsm + off)        = *(const uint4*)(g_qh + src);
        *(uint4*)(fsm + 8192 + off) = *(const uint4*)(g_ql + src);
    }
    __syncthreads();
    unsigned qfh[4][4], qfl[4][4];
#pragma unroll
    for (int kc = 0; kc < 4; kc++) {
        int qr = warp * 16 + (lane & 15);
        unsigned qoff = qr * 128 +
            (((unsigned)((2 * kc + (lane >> 4)) ^ (qr & 7))) << 4);
        ldsm4(qfh[kc], sb + qoff);
        ldsm4(qfl[kc], sb + 8192 + qoff);
    }
    __syncthreads();   // Q reads complete before KV overwrites stage 0

    auto issueKV = [&](int t) {
        unsigned stg = sb + (t & 1) * 32768;
        size_t rowb = base + (size_t)(t << 6) * 64;
        const __nv_bfloat16* s0 = g_kh + rowb;
        const __nv_bfloat16* s1 = g_kl + rowb;
        const __nv_bfloat16* s2 = g_vh + rowb;
        const __nv_bfloat16* s3 = g_vl + rowb;
#pragma unroll
        for (int i = 0; i < 16; i++) {
            int arr = i >> 2;
            int rem = (i & 3) * 128 + tid;
            int r = rem >> 3, ch = rem & 7;
            const __nv_bfloat16* sp = (arr == 0) ? s0 : (arr == 1) ? s1
                                     : (arr == 2) ? s2 : s3;
            cpa16(stg + arr * 8192 + r * 128 + ((ch ^ (r & 7)) << 4),
                  sp + (size_t)r * 64 + ch * 8);
        }
    };

    float o[8][4];
#pragma unroll
    for (int i = 0; i < 8; i++)
#pragma unroll
        for (int j = 0; j < 4; j++) o[i][j] = 0.f;
    float mr[2] = {-1e30f, -1e30f}, lr[2] = {0.f, 0.f};

    const int ntiles = blockIdx.x + 1;
    issueKV(0); CP_COMMIT();

    for (int t = 0; t < ntiles; t++) {
        if (t + 1 < ntiles) { issueKV(t + 1); CP_COMMIT(); CP_WAIT1(); }
        else                { CP_WAIT0(); }
        __syncthreads();   // stage t ready

        const unsigned stg = sb + (t & 1) * 32768;
        const unsigned sKh = stg, sKl = stg + 8192;
        const unsigned sVh = stg + 16384, sVl = stg + 24576;

        // ---- S = Q @ K^T ; single kb buffer, hi passes then lo pass ----
        float s[8][4];
#pragma unroll
        for (int i = 0; i < 8; i++)
#pragma unroll
            for (int j = 0; j < 4; j++) s[i][j] = 0.f;

#pragma unroll
        for (int kc = 0; kc < 4; kc++) {
            unsigned kb[4][4];
            unsigned koffs[4];
#pragma unroll
            for (int ntp = 0; ntp < 4; ntp++) {
                int kr = ntp * 16 + ((lane >> 4) << 3) + (lane & 7);
                koffs[ntp] = kr * 128 +
                    (((unsigned)((2 * kc + ((lane >> 3) & 1)) ^ (kr & 7))) << 4);
                ldsm4(kb[ntp], sKh + koffs[ntp]);
            }
#pragma unroll
            for (int ntp = 0; ntp < 4; ntp++) {
                mma16816(s[2*ntp],   qfh[kc], kb[ntp]);
                mma16816(s[2*ntp+1], qfh[kc], kb[ntp] + 2);
            }
#pragma unroll
            for (int ntp = 0; ntp < 4; ntp++) {
                mma16816(s[2*ntp],   qfl[kc], kb[ntp]);
                mma16816(s[2*ntp+1], qfl[kc], kb[ntp] + 2);
            }
#pragma unroll
            for (int ntp = 0; ntp < 4; ntp++)
                ldsm4(kb[ntp], sKl + koffs[ntp]);
#pragma unroll
            for (int ntp = 0; ntp < 4; ntp++) {
                mma16816(s[2*ntp],   qfh[kc], kb[ntp]);
                mma16816(s[2*ntp+1], qfh[kc], kb[ntp] + 2);
            }
        }

        if (t == ntiles - 1) {
            int row_lo = warp * 16 + g;
            int row_hi = row_lo + 8;
#pragma unroll
            for (int nt = 0; nt < 8; nt++) {
#pragma unroll
                for (int j = 0; j < 2; j++) {
                    int col = nt * 8 + 2 * t4 + j;
                    if (col > row_lo) s[nt][j]     = -1e30f;
                    if (col > row_hi) s[nt][2 + j] = -1e30f;
                }
            }
        }

        // ---- online softmax ----
#pragma unroll
        for (int hf = 0; hf < 2; hf++) {
            float mx = -1e30f;
#pragma unroll
            for (int nt = 0; nt < 8; nt++)
                mx = fmaxf(mx, fmaxf(s[nt][2*hf], s[nt][2*hf+1]));
            mx = fmaxf(mx, __shfl_xor_sync(0xffffffffu, mx, 1));
            mx = fmaxf(mx, __shfl_xor_sync(0xffffffffu, mx, 2));
            float mn   = fmaxf(mr[hf], mx);
            float corr = __expf(mr[hf] - mn);
            mr[hf] = mn;
            float rs = 0.f;
#pragma unroll
            for (int nt = 0; nt < 8; nt++) {
                float p0 = __expf(s[nt][2*hf]     - mn);
                float p1 = __expf(s[nt][2*hf + 1] - mn);
                s[nt][2*hf] = p0; s[nt][2*hf+1] = p1;
                rs += p0 + p1;
            }
            rs += __shfl_xor_sync(0xffffffffu, rs, 1);
            rs += __shfl_xor_sync(0xffffffffu, rs, 2);
            lr[hf] = lr[hf] * corr + rs;
#pragma unroll
            for (int dt = 0; dt < 8; dt++) {
                o[dt][2*hf]     *= corr;
                o[dt][2*hf + 1] *= corr;
            }
        }

        // ---- O += P @ V ; single vb buffer, hi passes then lo pass ----
#pragma unroll
        for (int kc = 0; kc < 4; kc++) {
            unsigned pah[4], pal[4];
#pragma unroll
            for (int q = 0; q < 2; q++) {
                float x0 = s[2*kc + q][0], x1 = s[2*kc + q][1];
                float x2 = s[2*kc + q][2], x3 = s[2*kc + q][3];
                float h0 = bfhi(x0), h1 = bfhi(x1);
                float h2 = bfhi(x2), h3 = bfhi(x3);
                pah[2*q]     = pk2(x0, x1);
                pah[2*q + 1] = pk2(x2, x3);
                pal[2*q]     = pk2(x0 - h0, x1 - h1);
                pal[2*q + 1] = pk2(x2 - h2, x3 - h3);
            }
            unsigned vb[4][4];
            unsigned voffs[4];
#pragma unroll
            for (int dtp = 0; dtp < 4; dtp++) {
                int vr = kc * 16 + (lane & 15);
                voffs[dtp] = vr * 128 +
                    (((unsigned)((2 * dtp + (lane >> 4)) ^ (vr & 7))) << 4);
                ldsm4t(vb[dtp], sVh + voffs[dtp]);
            }
#pragma unroll
            for (int dtp = 0; dtp < 4; dtp++) {
                mma16816(o[2*dtp],   pah, vb[dtp]);
                mma16816(o[2*dtp+1], pah, vb[dtp] + 2);
            }
#pragma unroll
            for (int dtp = 0; dtp < 4; dtp++) {
                mma16816(o[2*dtp],   pal, vb[dtp]);
                mma16816(o[2*dtp+1], pal, vb[dtp] + 2);
            }
#pragma unroll
            for (int dtp = 0; dtp < 4; dtp++)
                ldsm4t(vb[dtp], sVl + voffs[dtp]);
#pragma unroll
            for (int dtp = 0; dtp < 4; dtp++) {
                mma16816(o[2*dtp],   pah, vb[dtp]);
                mma16816(o[2*dtp+1], pah, vb[dtp] + 2);
            }
        }
        __syncthreads();   // all warps done reading stage t before refill
    }

    // epilogue: normalize, write segmented bf16 hi/lo to g_aoa
    const int bb = bh >> 4, h = bh & 15;
    const float inv0 = 1.f / lr[0], inv1 = 1.f / lr[1];
    const int mrow0 = q0 + warp * 16 + g;
#pragma unroll
    for (int dt = 0; dt < 8; dt++) {
        int col = h * 64 + dt * 8 + 2 * t4;
        size_t seg = (size_t)(col >> 4) * 32 + (col & 15);
        size_t i0 = ((size_t)(bb * S_ + mrow0))     * 2048 + seg;
        size_t i1 = ((size_t)(bb * S_ + mrow0 + 8)) * 2048 + seg;
        float v0 = o[dt][0] * inv0, v1 = o[dt][1] * inv0;
        float w0 = o[dt][2] * inv1, w1 = o[dt][3] * inv1;
        float h0 = bfhi(v0), h1 = bfhi(v1), e0 = bfhi(w0), e1 = bfhi(w1);
        *(unsigned*)&g_aoa[i0]      = pk2(v0, v1);
        *(unsigned*)&g_aoa[i0 + 16] = pk2(v0 - h0, v1 - h1);
        *(unsigned*)&g_aoa[i1]      = pk2(w0, w1);
        *(unsigned*)&g_aoa[i1 + 16] = pk2(w0 - e0, w1 - e1);
    }
}

// ---------------------------------------------------------------------------
extern "C" void kernel_launch(void* const* d_in, const int* in_sizes, int n_in,
                              void* d_out, int out_size)
{
    (void)in_sizes; (void)n_in; (void)out_size;
    const float* x      = (const float*)d_in[0];
    const float* W_attn = (const float*)d_in[1];
    const float* b_attn = (const float*)d_in[2];
    const float* W_proj = (const float*)d_in[3];
    const float* b_proj = (const float*)d_in[4];
    float* out = (float*)d_out;

    const int GSMEM = 3 * 32768;   // 98304
    const int FSMEM = 2 * 32768;   // 65536
    cudaFuncSetAttribute(tc_gemm5<N3_, true>,
        cudaFuncAttributeMaxDynamicSharedMemorySize, GSMEM);
    cudaFuncSetAttribute(tc_gemm5<C_, false>,
        cudaFuncAttributeMaxDynamicSharedMemorySize, GSMEM);
    cudaFuncSetAttribute(flash_attn_tc,
        cudaFuncAttributeMaxDynamicSharedMemorySize, FSMEM);

    conv_seg_x  <<<M_*C_/16/256, 256>>>(x);
    conv_plane<0><<<C_*N3_/8/256, 256>>>(W_attn);
    conv_plane<1><<<C_*C_/8/256,  256>>>(W_proj);
    tc_gemm5<N3_, true ><<<dim3(N3_/128, M_/128), 256, GSMEM>>>(b_attn, nullptr);
    flash_attn_tc<<<dim3(S_/64, B_*H_), 128, FSMEM>>>();
    tc_gemm5<C_,  false><<<dim3(C_/128,  M_/128), 256, GSMEM>>>(b_proj, out);
}

// round 15
// speedup vs baseline: 1.0696x; 1.0176x over previous
#include <cuda_runtime.h>
#include <cuda_bf16.h>
#include <cstdint>

#define B_  4
#define S_  2048
#define C_  1024
#define H_  16
#define D_  64
#define M_  (B_*S_)     // 8192
#define N3_ (3*C_)      // 3072

// Scratch (no allocations allowed)
__device__ __align__(16) __nv_bfloat16 g_qh[B_*H_*S_*D_];
__device__ __align__(16) __nv_bfloat16 g_ql[B_*H_*S_*D_];
__device__ __align__(16) __nv_bfloat16 g_kh[B_*H_*S_*D_];
__device__ __align__(16) __nv_bfloat16 g_kl[B_*H_*S_*D_];
__device__ __align__(16) __nv_bfloat16 g_vh[B_*H_*S_*D_];
__device__ __align__(16) __nv_bfloat16 g_vl[B_*H_*S_*D_];
// A operands, segmented: per row, per 16-k group: [16 hi | 16 lo] bf16
__device__ __align__(16) __nv_bfloat16 g_xa [M_*C_*2];
__device__ __align__(16) __nv_bfloat16 g_aoa[M_*C_*2];
// Weight planes (row-major [K][N]) bf16 hi/lo
__device__ __align__(16) __nv_bfloat16 g_wah[C_*N3_], g_wal[C_*N3_];
__device__ __align__(16) __nv_bfloat16 g_wph[C_*C_],  g_wpl[C_*C_];

// ---------------------------------------------------------------------------
// helpers
// ---------------------------------------------------------------------------
__device__ __forceinline__ unsigned pk2(float a, float b) {
    __nv_bfloat162 t = __floats2bfloat162_rn(a, b);
    return *reinterpret_cast<const unsigned*>(&t);
}
__device__ __forceinline__ float bfhi(float x) {
    return __bfloat162float(__float2bfloat16_rn(x));
}
__device__ __forceinline__ void ldsm4(unsigned r[4], unsigned addr) {
    asm volatile("ldmatrix.sync.aligned.m8n8.x4.shared.b16 {%0,%1,%2,%3}, [%4];\n"
        : "=r"(r[0]), "=r"(r[1]), "=r"(r[2]), "=r"(r[3]) : "r"(addr));
}
__device__ __forceinline__ void ldsm4t(unsigned r[4], unsigned addr) {
    asm volatile("ldmatrix.sync.aligned.m8n8.x4.trans.shared.b16 {%0,%1,%2,%3}, [%4];\n"
        : "=r"(r[0]), "=r"(r[1]), "=r"(r[2]), "=r"(r[3]) : "r"(addr));
}
__device__ __forceinline__ void mma16816(float c[4], const unsigned a[4],
                                         const unsigned b[2]) {
    asm volatile(
        "mma.sync.aligned.m16n8k16.row.col.f32.bf16.bf16.f32 "
        "{%0,%1,%2,%3}, {%4,%5,%6,%7}, {%8,%9}, {%0,%1,%2,%3};\n"
        : "+f"(c[0]), "+f"(c[1]), "+f"(c[2]), "+f"(c[3])
        : "r"(a[0]), "r"(a[1]), "r"(a[2]), "r"(a[3]), "r"(b[0]), "r"(b[1]));
}
__device__ __forceinline__ void cpa16(unsigned dst, const void* src) {
    asm volatile("cp.async.cg.shared.global [%0], [%1], 16;\n"
        :: "r"(dst), "l"(__cvta_generic_to_global(src)));
}
#define CP_COMMIT() asm volatile("cp.async.commit_group;\n" ::: "memory")
#define CP_WAIT1()  asm volatile("cp.async.wait_group 1;\n" ::: "memory")
#define CP_WAIT0()  asm volatile("cp.async.wait_group 0;\n" ::: "memory")

// ---------------------------------------------------------------------------
// Merged conversion kernel (one launch): blocks [0,2048) convert x into
// segmented layout; [2048,3584) W_attn planes; [3584,4096) W_proj planes.
// ---------------------------------------------------------------------------
__device__ __forceinline__ void conv_plane_body(
    const float* __restrict__ src, __nv_bfloat16* dh, __nv_bfloat16* dl,
    size_t i)
{
    const float4* p = (const float4*)(src + i);
    float4 a = p[0], b = p[1];
    uint4 u;
    u.x = pk2(a.x, a.y); u.y = pk2(a.z, a.w);
    u.z = pk2(b.x, b.y); u.w = pk2(b.z, b.w);
    *(uint4*)(dh + i) = u;
    u.x = pk2(a.x - bfhi(a.x), a.y - bfhi(a.y));
    u.y = pk2(a.z - bfhi(a.z), a.w - bfhi(a.w));
    u.z = pk2(b.x - bfhi(b.x), b.y - bfhi(b.y));
    u.w = pk2(b.z - bfhi(b.z), b.w - bfhi(b.w));
    *(uint4*)(dl + i) = u;
}

__global__ __launch_bounds__(256) void conv_all(
    const float* __restrict__ x, const float* __restrict__ Wa,
    const float* __restrict__ Wp)
{
    const int b = blockIdx.x;
    if (b < 2048) {
        size_t s = (size_t)b * 256 + threadIdx.x;
        const float4* p = (const float4*)(x + s * 16);
        float4 a = p[0], c = p[1], d = p[2], e = p[3];
        __nv_bfloat16* dst = g_xa + s * 32;
        uint4 u;
        u.x = pk2(a.x, a.y); u.y = pk2(a.z, a.w);
        u.z = pk2(c.x, c.y); u.w = pk2(c.z, c.w);
        *(uint4*)dst = u;
        u.x = pk2(a.x - bfhi(a.x), a.y - bfhi(a.y));
        u.y = pk2(a.z - bfhi(a.z), a.w - bfhi(a.w));
        u.z = pk2(c.x - bfhi(c.x), c.y - bfhi(c.y));
        u.w = pk2(c.z - bfhi(c.z), c.w - bfhi(c.w));
        *(uint4*)(dst + 16) = u;
        u.x = pk2(d.x, d.y); u.y = pk2(d.z, d.w);
        u.z = pk2(e.x, e.y); u.w = pk2(e.z, e.w);
        *(uint4*)(dst + 8) = u;
        u.x = pk2(d.x - bfhi(d.x), d.y - bfhi(d.y));
        u.y = pk2(d.z - bfhi(d.z), d.w - bfhi(d.w));
        u.z = pk2(e.x - bfhi(e.x), e.y - bfhi(e.y));
        u.w = pk2(e.z - bfhi(e.z), e.w - bfhi(e.w));
        *(uint4*)(dst + 24) = u;
    } else if (b < 3584) {
        size_t i = ((size_t)(b - 2048) * 256 + threadIdx.x) * 8;
        conv_plane_body(Wa, g_wah, g_wal, i);
    } else {
        size_t i = ((size_t)(b - 3584) * 256 + threadIdx.x) * 8;
        conv_plane_body(Wp, g_wph, g_wpl, i);
    }
}

// ---------------------------------------------------------------------------
// Tensor-core GEMM — EXACT R10 version (proven 337us / tensor 75.7%).
// bf16 hi/lo, BK=32 stages (32KB x 3 = 96KB dynamic smem),
// __launch_bounds__(256, 2): two CTAs per SM break barrier phase lock.
// ---------------------------------------------------------------------------
template<int LDB, bool SCATTER>
__global__ __launch_bounds__(256, 2) void tc_gemm5(
    const float* __restrict__ bias, float* __restrict__ out)
{
    extern __shared__ __align__(16) unsigned char smem[];
    const unsigned sb = (unsigned)__cvta_generic_to_shared(smem);
    const __nv_bfloat16* Aseg = SCATTER ? g_xa  : g_aoa;
    const __nv_bfloat16* Whp  = SCATTER ? g_wah : g_wph;
    const __nv_bfloat16* Wlp  = SCATTER ? g_wal : g_wpl;

    const int tid = threadIdx.x, lane = tid & 31, warp = tid >> 5;
    const int mw = warp & 1, nw = warp >> 1;
    const int m0 = blockIdx.y << 7, n0 = blockIdx.x << 7;

    const int ar = tid >> 3, ac = tid & 7;
    const char* aSrc0 = (const char*)Aseg + (size_t)(m0 + ar) * 4096 + ac * 16;
    const unsigned aDst0 = ar * 128 + ((ac ^ (ar & 7)) << 4);
    const int bk = tid >> 4, bn = tid & 15;
    const char* bSrcH = (const char*)Whp + ((size_t)bk * LDB + n0 + bn * 8) * 2;
    const char* bSrcL = (const char*)Wlp + ((size_t)bk * LDB + n0 + bn * 8) * 2;
    const unsigned bDst0 = 16384 + bk * 256 + ((bn ^ (bk & 7)) << 4);
    const size_t bHalf = (size_t)16 * LDB * 2;
    const size_t bStep = (size_t)32 * LDB * 2;

    float acc[16][4];
#pragma unroll
    for (int i = 0; i < 16; i++)
#pragma unroll
        for (int j = 0; j < 4; j++) acc[i][j] = 0.f;

    auto issue = [&](int kt) {
        unsigned st = sb + (kt % 3) * 32768;
        const char* as = aSrc0 + (size_t)kt * 128;
#pragma unroll
        for (int i = 0; i < 4; i++)
            cpa16(st + aDst0 + i * 4096, as + (size_t)i * 131072);
        const char* bs = bSrcH + (size_t)kt * bStep;
        cpa16(st + bDst0,        bs);
        cpa16(st + bDst0 + 4096, bs + bHalf);
        const char* bl_ = bSrcL + (size_t)kt * bStep;
        cpa16(st + bDst0 + 8192,        bl_);
        cpa16(st + bDst0 + 8192 + 4096, bl_ + bHalf);
    };

    issue(0); CP_COMMIT();
    issue(1); CP_COMMIT();

    const int KT = C_ / 32;   // 32
    for (int kt = 0; kt < KT; kt++) {
        CP_WAIT1();
        __syncthreads();
        if (kt + 2 < KT) issue(kt + 2);
        CP_COMMIT();

        const unsigned sA  = sb + (kt % 3) * 32768;
        const unsigned sBh = sA + 16384, sBl = sA + 24576;

#pragma unroll
        for (int kc = 0; kc < 2; kc++) {
            unsigned ah[4][4], al[4][4], bh[2][4], bl[2][4];
#pragma unroll
            for (int mt = 0; mt < 4; mt++) {
                int row = mw * 64 + mt * 16 + (lane & 15);
                unsigned b128 = sA + row * 128;
                int chH = kc * 4 + (lane >> 4);
                int chL = kc * 4 + 2 + (lane >> 4);
                ldsm4(ah[mt], b128 + ((chH ^ (row & 7)) << 4));
                ldsm4(al[mt], b128 + ((chL ^ (row & 7)) << 4));
            }
#pragma unroll
            for (int tp = 0; tp < 2; tp++) {
                int k  = kc * 16 + (lane & 15);
                int nc = nw * 4 + tp * 2 + (lane >> 4);
                unsigned off = k * 256 + ((nc ^ (k & 7)) << 4);
                ldsm4t(bh[tp], sBh + off);
                ldsm4t(bl[tp], sBl + off);
            }
#pragma unroll
            for (int mt = 0; mt < 4; mt++)
#pragma unroll
                for (int tp = 0; tp < 2; tp++)
#pragma unroll
                    for (int hf = 0; hf < 2; hf++)
                        mma16816(acc[mt*4 + tp*2 + hf], ah[mt], bh[tp] + hf*2);
#pragma unroll
            for (int mt = 0; mt < 4; mt++)
#pragma unroll
                for (int tp = 0; tp < 2; tp++)
#pragma unroll
                    for (int hf = 0; hf < 2; hf++)
                        mma16816(acc[mt*4 + tp*2 + hf], ah[mt], bl[tp] + hf*2);
#pragma unroll
            for (int mt = 0; mt < 4; mt++)
#pragma unroll
                for (int tp = 0; tp < 2; tp++)
#pragma unroll
                    for (int hf = 0; hf < 2; hf++)
                        mma16816(acc[mt*4 + tp*2 + hf], al[mt], bh[tp] + hf*2);
        }
    }

    const int g  = lane >> 2;
    const int cp = (lane & 3) << 1;
    if (SCATTER) {
        const int part = n0 >> 10;
        __nv_bfloat16* dH = (part == 0) ? g_qh : (part == 1) ? g_kh : g_vh;
        __nv_bfloat16* dL = (part == 0) ? g_ql : (part == 1) ? g_kl : g_vl;
        const float fs = (part == 0) ? 0.125f : 1.0f;
#pragma unroll
        for (int mt = 0; mt < 4; mt++) {
#pragma unroll
            for (int nt = 0; nt < 4; nt++) {
                int n = n0 + nw * 32 + nt * 8 + cp;
                int c = n & (C_ - 1);
                int hh = c >> 6, d = c & 63;
                float b0 = bias[n], b1 = bias[n + 1];
                float* a4 = acc[mt * 4 + nt];
#pragma unroll
                for (int rr = 0; rr < 2; rr++) {
                    int m  = m0 + mw * 64 + mt * 16 + g + rr * 8;
                    int bb = m >> 11, ss = m & (S_ - 1);
                    float v0 = (a4[rr * 2] + b0) * fs;
                    float v1 = (a4[rr * 2 + 1] + b1) * fs;
                    float h0 = bfhi(v0), h1 = bfhi(v1);
                    size_t idx = (((size_t)(bb * H_ + hh)) * S_ + ss) * D_ + d;
                    *(unsigned*)&dH[idx] = pk2(v0, v1);
                    *(unsigned*)&dL[idx] = pk2(v0 - h0, v1 - h1);
                }
            }
        }
    } else {
#pragma unroll
        for (int mt = 0; mt < 4; mt++) {
#pragma unroll
            for (int nt = 0; nt < 4; nt++) {
                int n = n0 + nw * 32 + nt * 8 + cp;
                float b0 = bias[n], b1 = bias[n + 1];
                float* a4 = acc[mt * 4 + nt];
#pragma unroll
                for (int rr = 0; rr < 2; rr++) {
                    int m = m0 + mw * 64 + mt * 16 + g + rr * 8;
                    float2 o = make_float2(a4[rr * 2] + b0, a4[rr * 2 + 1] + b1);
                    *(float2*)&out[(size_t)m * C_ + n] = o;
                }
            }
        }
    }
}

// ---------------------------------------------------------------------------
// Tensor-core flash attention v3 (R13 body) + HEAVY-FIRST tile ordering:
// qt = 31 - blockIdx.x, so the longest (qt+1)-tile CTAs schedule first and
// the stragglers at the end of the grid are the 1-tile CTAs (LPT schedule).
// Q held in registers; smem = 2 x 32KB KV ring -> 3 CTAs/SM.
// ---------------------------------------------------------------------------
__global__ __launch_bounds__(128, 3) void flash_attn_tc()
{
    extern __shared__ __align__(16) unsigned char fsm[];
    const unsigned sb = (unsigned)__cvta_generic_to_shared(fsm);

    const int tid  = threadIdx.x;
    const int lane = tid & 31, warp = tid >> 5;
    const int bh = blockIdx.y;
    const int qt = (S_ / 64 - 1) - blockIdx.x;   // heavy tiles first
    const int q0 = qt << 6;
    const size_t base = (size_t)bh * (S_ * D_);
    const int g = lane >> 2, t4 = lane & 3;

    // ---- one-time Q load: bounce through stage-0 smem, ldsm to registers --
#pragma unroll
    for (int i = 0; i < 4; i++) {
        int f = i * 128 + tid;
        int r = f >> 3, ch = f & 7;
        unsigned off = r * 128 + (((unsigned)(ch ^ (r & 7))) << 4);
        size_t src = base + (size_t)(q0 + r) * 64 + ch * 8;
        *(uint4*)(fsm + off)        = *(const uint4*)(g_qh + src);
        *(uint4*)(fsm + 8192 + off) = *(const uint4*)(g_ql + src);
    }
    __syncthreads();
    unsigned qfh[4][4], qfl[4][4];
#pragma unroll
    for (int kc = 0; kc < 4; kc++) {
        int qr = warp * 16 + (lane & 15);
        unsigned qoff = qr * 128 +
            (((unsigned)((2 * kc + (lane >> 4)) ^ (qr & 7))) << 4);
        ldsm4(qfh[kc], sb + qoff);
        ldsm4(qfl[kc], sb + 8192 + qoff);
    }
    __syncthreads();   // Q reads complete before KV overwrites stage 0

    auto issueKV = [&](int t) {
        unsigned stg = sb + (t & 1) * 32768;
        size_t rowb = base + (size_t)(t << 6) * 64;
        const __nv_bfloat16* s0 = g_kh + rowb;
        const __nv_bfloat16* s1 = g_kl + rowb;
        const __nv_bfloat16* s2 = g_vh + rowb;
        const __nv_bfloat16* s3 = g_vl + rowb;
#pragma unroll
        for (int i = 0; i < 16; i++) {
            int arr = i >> 2;
            int rem = (i & 3) * 128 + tid;
            int r = rem >> 3, ch = rem & 7;
            const __nv_bfloat16* sp = (arr == 0) ? s0 : (arr == 1) ? s1
                                     : (arr == 2) ? s2 : s3;
            cpa16(stg + arr * 8192 + r * 128 + ((ch ^ (r & 7)) << 4),
                  sp + (size_t)r * 64 + ch * 8);
        }
    };

    float o[8][4];
#pragma unroll
    for (int i = 0; i < 8; i++)
#pragma unroll
        for (int j = 0; j < 4; j++) o[i][j] = 0.f;
    float mr[2] = {-1e30f, -1e30f}, lr[2] = {0.f, 0.f};

    const int ntiles = qt + 1;
    issueKV(0); CP_COMMIT();

    for (int t = 0; t < ntiles; t++) {
        if (t + 1 < ntiles) { issueKV(t + 1); CP_COMMIT(); CP_WAIT1(); }
        else                { CP_WAIT0(); }
        __syncthreads();   // stage t ready

        const unsigned stg = sb + (t & 1) * 32768;
        const unsigned sKh = stg, sKl = stg + 8192;
        const unsigned sVh = stg + 16384, sVl = stg + 24576;

        // ---- S = Q @ K^T ; single kb buffer, hi passes then lo pass ----
        float s[8][4];
#pragma unroll
        for (int i = 0; i < 8; i++)
#pragma unroll
            for (int j = 0; j < 4; j++) s[i][j] = 0.f;

#pragma unroll
        for (int kc = 0; kc < 4; kc++) {
            unsigned kb[4][4];
            unsigned koffs[4];
#pragma unroll
            for (int ntp = 0; ntp < 4; ntp++) {
                int kr = ntp * 16 + ((lane >> 4) << 3) + (lane & 7);
                koffs[ntp] = kr * 128 +
                    (((unsigned)((2 * kc + ((lane >> 3) & 1)) ^ (kr & 7))) << 4);
                ldsm4(kb[ntp], sKh + koffs[ntp]);
            }
#pragma unroll
            for (int ntp = 0; ntp < 4; ntp++) {
                mma16816(s[2*ntp],   qfh[kc], kb[ntp]);
                mma16816(s[2*ntp+1], qfh[kc], kb[ntp] + 2);
            }
#pragma unroll
            for (int ntp = 0; ntp < 4; ntp++) {
                mma16816(s[2*ntp],   qfl[kc], kb[ntp]);
                mma16816(s[2*ntp+1], qfl[kc], kb[ntp] + 2);
            }
#pragma unroll
            for (int ntp = 0; ntp < 4; ntp++)
                ldsm4(kb[ntp], sKl + koffs[ntp]);
#pragma unroll
            for (int ntp = 0; ntp < 4; ntp++) {
                mma16816(s[2*ntp],   qfh[kc], kb[ntp]);
                mma16816(s[2*ntp+1], qfh[kc], kb[ntp] + 2);
            }
        }

        if (t == ntiles - 1) {
            int row_lo = warp * 16 + g;
            int row_hi = row_lo + 8;
#pragma unroll
            for (int nt = 0; nt < 8; nt++) {
#pragma unroll
                for (int j = 0; j < 2; j++) {
                    int col = nt * 8 + 2 * t4 + j;
                    if (col > row_lo) s[nt][j]     = -1e30f;
                    if (col > row_hi) s[nt][2 + j] = -1e30f;
                }
            }
        }

        // ---- online softmax ----
#pragma unroll
        for (int hf = 0; hf < 2; hf++) {
            float mx = -1e30f;
#pragma unroll
            for (int nt = 0; nt < 8; nt++)
                mx = fmaxf(mx, fmaxf(s[nt][2*hf], s[nt][2*hf+1]));
            mx = fmaxf(mx, __shfl_xor_sync(0xffffffffu, mx, 1));
            mx = fmaxf(mx, __shfl_xor_sync(0xffffffffu, mx, 2));
            float mn   = fmaxf(mr[hf], mx);
            float corr = __expf(mr[hf] - mn);
            mr[hf] = mn;
            float rs = 0.f;
#pragma unroll
            for (int nt = 0; nt < 8; nt++) {
                float p0 = __expf(s[nt][2*hf]     - mn);
                float p1 = __expf(s[nt][2*hf + 1] - mn);
                s[nt][2*hf] = p0; s[nt][2*hf+1] = p1;
                rs += p0 + p1;
            }
            rs += __shfl_xor_sync(0xffffffffu, rs, 1);
            rs += __shfl_xor_sync(0xffffffffu, rs, 2);
            lr[hf] = lr[hf] * corr + rs;
#pragma unroll
            for (int dt = 0; dt < 8; dt++) {
                o[dt][2*hf]     *= corr;
                o[dt][2*hf + 1] *= corr;
            }
        }

        // ---- O += P @ V ; single vb buffer, hi passes then lo pass ----
#pragma unroll
        for (int kc = 0; kc < 4; kc++) {
            unsigned pah[4], pal[4];
#pragma unroll
            for (int q = 0; q < 2; q++) {
                float x0 = s[2*kc + q][0], x1 = s[2*kc + q][1];
                float x2 = s[2*kc + q][2], x3 = s[2*kc + q][3];
                float h0 = bfhi(x0), h1 = bfhi(x1);
                float h2 = bfhi(x2), h3 = bfhi(x3);
                pah[2*q]     = pk2(x0, x1);
                pah[2*q + 1] = pk2(x2, x3);
                pal[2*q]     = pk2(x0 - h0, x1 - h1);
                pal[2*q + 1] = pk2(x2 - h2, x3 - h3);
            }
            unsigned vb[4][4];
            unsigned voffs[4];
#pragma unroll
            for (int dtp = 0; dtp < 4; dtp++) {
                int vr = kc * 16 + (lane & 15);
                voffs[dtp] = vr * 128 +
                    (((unsigned)((2 * dtp + (lane >> 4)) ^ (vr & 7))) << 4);
                ldsm4t(vb[dtp], sVh + voffs[dtp]);
            }
#pragma unroll
            for (int dtp = 0; dtp < 4; dtp++) {
                mma16816(o[2*dtp],   pah, vb[dtp]);
                mma16816(o[2*dtp+1], pah, vb[dtp] + 2);
            }
#pragma unroll
            for (int dtp = 0; dtp < 4; dtp++) {
                mma16816(o[2*dtp],   pal, vb[dtp]);
                mma16816(o[2*dtp+1], pal, vb[dtp] + 2);
            }
#pragma unroll
            for (int dtp = 0; dtp < 4; dtp++)
                ldsm4t(vb[dtp], sVl + voffs[dtp]);
#pragma unroll
            for (int dtp = 0; dtp < 4; dtp++) {
                mma16816(o[2*dtp],   pah, vb[dtp]);
                mma16816(o[2*dtp+1], pah, vb[dtp] + 2);
            }
        }
        __syncthreads();   // all warps done reading stage t before refill
    }

    // epilogue: normalize, write segmented bf16 hi/lo to g_aoa
    const int bb = bh >> 4, h = bh & 15;
    const float inv0 = 1.f / lr[0], inv1 = 1.f / lr[1];
    const int mrow0 = q0 + warp * 16 + g;
#pragma unroll
    for (int dt = 0; dt < 8; dt++) {
        int col = h * 64 + dt * 8 + 2 * t4;
        size_t seg = (size_t)(col >> 4) * 32 + (col & 15);
        size_t i0 = ((size_t)(bb * S_ + mrow0))     * 2048 + seg;
        size_t i1 = ((size_t)(bb * S_ + mrow0 + 8)) * 2048 + seg;
        float v0 = o[dt][0] * inv0, v1 = o[dt][1] * inv0;
        float w0 = o[dt][2] * inv1, w1 = o[dt][3] * inv1;
        float h0 = bfhi(v0), h1 = bfhi(v1), e0 = bfhi(w0), e1 = bfhi(w1);
        *(unsigned*)&g_aoa[i0]      = pk2(v0, v1);
        *(unsigned*)&g_aoa[i0 + 16] = pk2(v0 - h0, v1 - h1);
        *(unsigned*)&g_aoa[i1]      = pk2(w0, w1);
        *(unsigned*)&g_aoa[i1 + 16] = pk2(w0 - e0, w1 - e1);
    }
}

// ---------------------------------------------------------------------------
extern "C" void kernel_launch(void* const* d_in, const int* in_sizes, int n_in,
                              void* d_out, int out_size)
{
    (void)in_sizes; (void)n_in; (void)out_size;
    const float* x      = (const float*)d_in[0];
    const float* W_attn = (const float*)d_in[1];
    const float* b_attn = (const float*)d_in[2];
    const float* W_proj = (const float*)d_in[3];
    const float* b_proj = (const float*)d_in[4];
    float* out = (float*)d_out;

    const int GSMEM = 3 * 32768;   // 98304
    const int FSMEM = 2 * 32768;   // 65536
    cudaFuncSetAttribute(tc_gemm5<N3_, true>,
        cudaFuncAttributeMaxDynamicSharedMemorySize, GSMEM);
    cudaFuncSetAttribute(tc_gemm5<C_, false>,
        cudaFuncAttributeMaxDynamicSharedMemorySize, GSMEM);
    cudaFuncSetAttribute(flash_attn_tc,
        cudaFuncAttributeMaxDynamicSharedMemorySize, FSMEM);

    conv_all<<<4096, 256>>>(x, W_attn, W_proj);
    tc_gemm5<N3_, true ><<<dim3(N3_/128, M_/128), 256, GSMEM>>>(b_attn, nullptr);
    flash_attn_tc<<<dim3(S_/64, B_*H_), 128, FSMEM>>>();
    tc_gemm5<C_,  false><<<dim3(C_/128,  M_/128), 256, GSMEM>>>(b_proj, out);
}